// round 2
// baseline (speedup 1.0000x reference)
#include <cuda_runtime.h>
#include <math.h>

#define B_   16
#define S_   1024
#define D_   768
#define NH_  4
#define HD_  192
#define DFF_ 3072
#define NL_  2
#define C_   3
#define BS_  (B_*S_)     // 16384
#define TD_  (3*D_)      // 2304

// ---- output layout (floats) ----
#define O_LA  ((size_t)0)
#define O_LO  ((size_t)49152)
#define O_X   ((size_t)98304)
#define O_SE1 ((size_t)12681216)
#define O_SE2 ((size_t)25264128)
#define O_IA  ((size_t)37847040)
#define O_IO  ((size_t)37847072)
#define O_E1  ((size_t)37847104)
#define O_E2  ((size_t)37859392)

// ---- scratch (device globals; no allocation allowed) ----
__device__ float g_qkv[(size_t)BS_*TD_];              // 151 MB
__device__ float g_scores[(size_t)B_*NH_*S_*S_];      // 268 MB
__device__ float g_m[B_*NH_*S_];
__device__ float g_z[B_*NH_*S_];
__device__ float g_w[B_*NH_*S_];
__device__ float g_ctxmean[B_*D_];
__device__ float g_e1[B_*D_];
__device__ float g_e2[B_*D_];
__device__ int   g_idx[B_];
__device__ float g_h1[(size_t)BS_*D_];
__device__ float g_h2[(size_t)BS_*D_];
__device__ float g_inter[(size_t)BS_*DFF_];           // 201 MB
__device__ float g_tmp[(size_t)BS_*D_];

// ============================================================
// Generic tiled SGEMM: C[m,n] = sum_k A[m,k]*B[n,k] + bias[n] (+epilogue)
// 128x128 tile, BK=8, 256 threads, 8x8 per thread.
// EPI: 0=bias only, 1=bias+exact GELU, 2=bias+residual
// ============================================================
template<int EPI>
__global__ void __launch_bounds__(256) sgemm_kernel(
    const float* __restrict__ A, int lda,
    const float* __restrict__ Bw, int ldb,
    float* __restrict__ C, int ldc,
    const float* __restrict__ bias,
    const float* __restrict__ resid,
    int K)
{
    __shared__ float As[8][128];
    __shared__ float Bs[8][128];
    const int tid = threadIdx.x;
    const int m0 = blockIdx.y * 128;
    const int n0 = blockIdx.x * 128;
    const int lr = tid >> 1;
    const int lc = (tid & 1) * 4;
    const float* Ap = A + (size_t)(m0 + lr) * lda + lc;
    const float* Bp = Bw + (size_t)(n0 + lr) * ldb + lc;
    const int ty = tid >> 4;
    const int tx = tid & 15;

    float acc[8][8];
#pragma unroll
    for (int i = 0; i < 8; i++)
#pragma unroll
        for (int j = 0; j < 8; j++) acc[i][j] = 0.f;

    for (int k0 = 0; k0 < K; k0 += 8) {
        float4 av = *(const float4*)(Ap + k0);
        float4 bv = *(const float4*)(Bp + k0);
        __syncthreads();
        As[lc+0][lr] = av.x; As[lc+1][lr] = av.y; As[lc+2][lr] = av.z; As[lc+3][lr] = av.w;
        Bs[lc+0][lr] = bv.x; Bs[lc+1][lr] = bv.y; Bs[lc+2][lr] = bv.z; Bs[lc+3][lr] = bv.w;
        __syncthreads();
#pragma unroll
        for (int kk = 0; kk < 8; kk++) {
            float a[8], b[8];
            *(float4*)&a[0] = *(const float4*)&As[kk][ty*8];
            *(float4*)&a[4] = *(const float4*)&As[kk][ty*8+4];
            *(float4*)&b[0] = *(const float4*)&Bs[kk][tx*8];
            *(float4*)&b[4] = *(const float4*)&Bs[kk][tx*8+4];
#pragma unroll
            for (int i = 0; i < 8; i++)
#pragma unroll
                for (int j = 0; j < 8; j++)
                    acc[i][j] += a[i] * b[j];
        }
    }

#pragma unroll
    for (int i = 0; i < 8; i++) {
        int row = m0 + ty*8 + i;
#pragma unroll
        for (int j = 0; j < 8; j++) {
            int col = n0 + tx*8 + j;
            float v = acc[i][j] + bias[col];
            if (EPI == 1) v = 0.5f * v * (1.0f + erff(v * 0.70710678118654752f));
            if (EPI == 2) v += resid[(size_t)row * ldc + col];
            C[(size_t)row * ldc + col] = v;
        }
    }
}

// ============================================================
// Attention scores: scores[z,q,k] = (q_vec . k_vec)/sqrt(hd), mask -> -1e30
// z = b*NH + h. Same tile structure as sgemm, M=N=1024, K=192.
// ============================================================
__global__ void __launch_bounds__(256) scores_kernel(const int* __restrict__ mask)
{
    __shared__ float As[8][128];
    __shared__ float Bs[8][128];
    const int z = blockIdx.z;
    const int b = z >> 2, h = z & 3;
    const float* A  = g_qkv + (size_t)b * S_ * TD_ + h * HD_;          // Q
    const float* Bw = g_qkv + (size_t)b * S_ * TD_ + D_ + h * HD_;     // K
    float* C = g_scores + (size_t)z * S_ * S_;

    const int tid = threadIdx.x;
    const int m0 = blockIdx.y * 128;
    const int n0 = blockIdx.x * 128;
    const int lr = tid >> 1;
    const int lc = (tid & 1) * 4;
    const float* Ap = A  + (size_t)(m0 + lr) * TD_ + lc;
    const float* Bp = Bw + (size_t)(n0 + lr) * TD_ + lc;
    const int ty = tid >> 4;
    const int tx = tid & 15;

    float acc[8][8];
#pragma unroll
    for (int i = 0; i < 8; i++)
#pragma unroll
        for (int j = 0; j < 8; j++) acc[i][j] = 0.f;

    for (int k0 = 0; k0 < HD_; k0 += 8) {
        float4 av = *(const float4*)(Ap + k0);
        float4 bv = *(const float4*)(Bp + k0);
        __syncthreads();
        As[lc+0][lr] = av.x; As[lc+1][lr] = av.y; As[lc+2][lr] = av.z; As[lc+3][lr] = av.w;
        Bs[lc+0][lr] = bv.x; Bs[lc+1][lr] = bv.y; Bs[lc+2][lr] = bv.z; Bs[lc+3][lr] = bv.w;
        __syncthreads();
#pragma unroll
        for (int kk = 0; kk < 8; kk++) {
            float a[8], bb[8];
            *(float4*)&a[0]  = *(const float4*)&As[kk][ty*8];
            *(float4*)&a[4]  = *(const float4*)&As[kk][ty*8+4];
            *(float4*)&bb[0] = *(const float4*)&Bs[kk][tx*8];
            *(float4*)&bb[4] = *(const float4*)&Bs[kk][tx*8+4];
#pragma unroll
            for (int i = 0; i < 8; i++)
#pragma unroll
                for (int j = 0; j < 8; j++)
                    acc[i][j] += a[i] * bb[j];
        }
    }

    const float scale = 0.07216878364870322f;  // 1/sqrt(192)
#pragma unroll
    for (int i = 0; i < 8; i++) {
        int row = m0 + ty*8 + i;
#pragma unroll
        for (int j = 0; j < 8; j++) {
            int col = n0 + tx*8 + j;
            float v = acc[i][j] * scale;
            if (mask[b * S_ + col] == 0) v = -1e30f;
            C[(size_t)row * S_ + col] = v;
        }
    }
}

// row max + exp-sum per score row
__global__ void rowstats_kernel()
{
    const int row = blockIdx.x;
    const int tid = threadIdx.x;
    const float* r = g_scores + (size_t)row * S_;
    float v0 = r[tid], v1 = r[tid+256], v2 = r[tid+512], v3 = r[tid+768];
    __shared__ float red[256];
    float mx = fmaxf(fmaxf(v0, v1), fmaxf(v2, v3));
    red[tid] = mx; __syncthreads();
    for (int st = 128; st > 0; st >>= 1) { if (tid < st) red[tid] = fmaxf(red[tid], red[tid+st]); __syncthreads(); }
    float m = red[0];
    __syncthreads();
    float se = __expf(v0 - m) + __expf(v1 - m) + __expf(v2 - m) + __expf(v3 - m);
    red[tid] = se; __syncthreads();
    for (int st = 128; st > 0; st >>= 1) { if (tid < st) red[tid] += red[tid+st]; __syncthreads(); }
    if (tid == 0) { g_m[row] = m; g_z[row] = red[0]; }
}

// w[z,k] = sum_q exp(s[q,k]-m_q)/z_q
__global__ void colsum_kernel()
{
    const int z = blockIdx.x;
    const int tid = threadIdx.x;
    __shared__ float sm[S_];
    __shared__ float sz[S_];
    for (int q = tid; q < S_; q += 256) { sm[q] = g_m[z*S_+q]; sz[q] = 1.0f / g_z[z*S_+q]; }
    __syncthreads();
    float acc[4] = {0.f, 0.f, 0.f, 0.f};
    const float* sc = g_scores + (size_t)z * S_ * S_;
    for (int q = 0; q < S_; q++) {
        float mq = sm[q], rz = sz[q];
        const float* row = sc + (size_t)q * S_;
#pragma unroll
        for (int i = 0; i < 4; i++)
            acc[i] += __expf(row[tid + i*256] - mq) * rz;
    }
#pragma unroll
    for (int i = 0; i < 4; i++) g_w[z*S_ + tid + i*256] = acc[i];
}

// ctx_mean[b, h*HD+d] = (1/S) sum_k w[z,k] * V[b,k,h*HD+d]
__global__ void ctxmean_kernel()
{
    const int z = blockIdx.x;
    const int b = z >> 2, h = z & 3;
    const int d = threadIdx.x;   // 0..191
    __shared__ float w[S_];
    for (int k = d; k < S_; k += 192) w[k] = g_w[z*S_+k];
    __syncthreads();
    float acc = 0.f;
    const float* vb = g_qkv + (size_t)b * S_ * TD_ + 2*D_ + h*HD_ + d;
    for (int k = 0; k < S_; k++) acc += w[k] * vb[(size_t)k * TD_];
    g_ctxmean[b*D_ + h*HD_ + d] = acc * (1.0f / S_);
}

__global__ void idx_kernel(const int* __restrict__ mask)
{
    const int b = blockIdx.x, tid = threadIdx.x;
    __shared__ int red[256];
    int s = 0;
    for (int k = tid; k < S_; k += 256) s += mask[b*S_ + k];
    red[tid] = s; __syncthreads();
    for (int st = 128; st > 0; st >>= 1) { if (tid < st) red[tid] += red[tid+st]; __syncthreads(); }
    if (tid == 0) g_idx[b] = red[0] - 1;
}

// embedding = ctx_mean @ Wout^T + bout ; e1/e2 ; imp_asp/imp_opi
__global__ void embed_kernel(
    const float* __restrict__ Wout, const float* __restrict__ bout,
    const float* __restrict__ Wasp, const float* __restrict__ basp,
    const float* __restrict__ Wopi, const float* __restrict__ bopi,
    const float* __restrict__ Wia,  const float* __restrict__ bia,
    const float* __restrict__ Wio,  const float* __restrict__ bio,
    float* __restrict__ out)
{
    const int b = blockIdx.x, tid = threadIdx.x;
    __shared__ float cm[D_], emb[D_], e1s[D_], e2s[D_];
    for (int d = tid; d < D_; d += 256) cm[d] = g_ctxmean[b*D_ + d];
    __syncthreads();
    for (int n = tid; n < D_; n += 256) {
        float a = bout[n];
        const float* wr = Wout + (size_t)n * D_;
        for (int d = 0; d < D_; d++) a += cm[d] * wr[d];
        emb[n] = a;
    }
    __syncthreads();
    for (int n = tid; n < D_; n += 256) {
        float a = basp[n], o = bopi[n];
        const float* wa = Wasp + (size_t)n * D_;
        const float* wo = Wopi + (size_t)n * D_;
        for (int d = 0; d < D_; d++) { a += emb[d] * wa[d]; o += emb[d] * wo[d]; }
        e1s[n] = a; e2s[n] = o;
    }
    __syncthreads();
    for (int d = tid; d < D_; d += 256) {
        g_e1[b*D_ + d] = e1s[d];
        g_e2[b*D_ + d] = e2s[d];
        out[O_E1 + (size_t)b*D_ + d] = e1s[d];
        out[O_E2 + (size_t)b*D_ + d] = e2s[d];
    }
    if (tid < 2) {
        float a = bia[tid];
        const float* w = Wia + (size_t)tid * D_;
        for (int d = 0; d < D_; d++) a += e1s[d] * w[d];
        out[O_IA + b*2 + tid] = a;
    } else if (tid < 4) {
        int c = tid - 2;
        float a = bio[c];
        const float* w = Wio + (size_t)c * D_;
        for (int d = 0; d < D_; d++) a += e2s[d] * w[d];
        out[O_IO + b*2 + c] = a;
    }
}

// se buffers: scatter e1 at s=0, e2 at s=idx (order differs only if idx==0)
__global__ void build_se_kernel(const float* __restrict__ x)
{
    const int blk = blockIdx.x;
    const int b = blk >> 10, s = blk & 1023;
    const int idx = g_idx[b];
#pragma unroll
    for (int i = 0; i < 3; i++) {
        int d = threadIdx.x + i * 256;
        float xv = x[(size_t)blk * D_ + d];
        float e1v = g_e1[b*D_ + d], e2v = g_e2[b*D_ + d];
        float v1 = (s == idx) ? e2v : ((s == 0) ? e1v : xv);  // [0]=e1 then [idx]=e2
        float v2 = (s == 0) ? e1v : ((s == idx) ? e2v : xv);  // [idx]=e2 then [0]=e1
        g_h1[(size_t)blk * D_ + d] = v1;
        g_h2[(size_t)blk * D_ + d] = v2;
    }
}

__global__ void ln_kernel(const float* __restrict__ in,
                          const float* __restrict__ g, const float* __restrict__ bt,
                          float* __restrict__ outp)
{
    const int row = blockIdx.x, tid = threadIdx.x;
    const float* r = in + (size_t)row * D_;
    float v0 = r[tid], v1 = r[tid+256], v2 = r[tid+512];
    __shared__ float red[256];
    red[tid] = v0 + v1 + v2; __syncthreads();
    for (int st = 128; st > 0; st >>= 1) { if (tid < st) red[tid] += red[tid+st]; __syncthreads(); }
    float mean = red[0] * (1.0f / D_);
    __syncthreads();
    float d0 = v0 - mean, d1 = v1 - mean, d2 = v2 - mean;
    red[tid] = d0*d0 + d1*d1 + d2*d2; __syncthreads();
    for (int st = 128; st > 0; st >>= 1) { if (tid < st) red[tid] += red[tid+st]; __syncthreads(); }
    float rstd = rsqrtf(red[0] * (1.0f / D_) + 1e-12f);
    float* o = outp + (size_t)row * D_;
    o[tid]     = d0 * rstd * g[tid]     + bt[tid];
    o[tid+256] = d1 * rstd * g[tid+256] + bt[tid+256];
    o[tid+512] = d2 * rstd * g[tid+512] + bt[tid+512];
}

__global__ void logits_kernel(const float* __restrict__ in, const float* __restrict__ W,
                              const float* __restrict__ bias, float* __restrict__ outp)
{
    const int row = blockIdx.x, tid = threadIdx.x;
    __shared__ float srow[D_];
    const float* r = in + (size_t)row * D_;
    srow[tid] = r[tid]; srow[tid+256] = r[tid+256]; srow[tid+512] = r[tid+512];
    __syncthreads();
    float a0 = 0.f, a1 = 0.f, a2 = 0.f;
    for (int d = tid; d < D_; d += 256) {
        float x = srow[d];
        a0 += x * W[d]; a1 += x * W[D_ + d]; a2 += x * W[2*D_ + d];
    }
    __shared__ float red[3][256];
    red[0][tid] = a0; red[1][tid] = a1; red[2][tid] = a2;
    __syncthreads();
    for (int st = 128; st > 0; st >>= 1) {
        if (tid < st) {
            red[0][tid] += red[0][tid+st];
            red[1][tid] += red[1][tid+st];
            red[2][tid] += red[2][tid+st];
        }
        __syncthreads();
    }
    if (tid < 3) outp[(size_t)row * C_ + tid] = red[tid][0] + bias[tid];
}

// ============================================================
extern "C" void kernel_launch(void* const* d_in, const int* in_sizes, int n_in,
                              void* d_out, int out_size)
{
    const float* x        = (const float*)d_in[0];
    const int*   mask     = (const int*)  d_in[1];
    const float* mha_in_w = (const float*)d_in[2];
    const float* mha_in_b = (const float*)d_in[3];
    const float* mha_out_w= (const float*)d_in[4];
    const float* mha_out_b= (const float*)d_in[5];
    const float* asp_w    = (const float*)d_in[6];
    const float* asp_b    = (const float*)d_in[7];
    const float* opi_w    = (const float*)d_in[8];
    const float* opi_b    = (const float*)d_in[9];
    const float* ia_w     = (const float*)d_in[10];
    const float* ia_b     = (const float*)d_in[11];
    const float* io_w     = (const float*)d_in[12];
    const float* io_b     = (const float*)d_in[13];
    const float* fwd_iw   = (const float*)d_in[14];
    const float* fwd_ib   = (const float*)d_in[15];
    const float* fwd_ow   = (const float*)d_in[16];
    const float* fwd_ob   = (const float*)d_in[17];
    const float* fwd_g    = (const float*)d_in[18];
    const float* fwd_bt   = (const float*)d_in[19];
    const float* rev_iw   = (const float*)d_in[20];
    const float* rev_ib   = (const float*)d_in[21];
    const float* rev_ow   = (const float*)d_in[22];
    const float* rev_ob   = (const float*)d_in[23];
    const float* rev_g    = (const float*)d_in[24];
    const float* rev_bt   = (const float*)d_in[25];
    const float* cls_a_w  = (const float*)d_in[26];
    const float* cls_a_b  = (const float*)d_in[27];
    const float* cls_o_w  = (const float*)d_in[28];
    const float* cls_o_b  = (const float*)d_in[29];
    float* out = (float*)d_out;

    float *qkvp, *h1, *h2, *inter, *tmp;
    cudaGetSymbolAddress((void**)&qkvp,  g_qkv);
    cudaGetSymbolAddress((void**)&h1,    g_h1);
    cudaGetSymbolAddress((void**)&h2,    g_h2);
    cudaGetSymbolAddress((void**)&inter, g_inter);
    cudaGetSymbolAddress((void**)&tmp,   g_tmp);

    // 1) QKV projection  [16384,768] @ [2304,768]^T
    sgemm_kernel<0><<<dim3(TD_/128, BS_/128), 256>>>(x, D_, mha_in_w, D_, qkvp, TD_, mha_in_b, nullptr, D_);

    // 2) attention scores + softmax stats + column-sum weights + ctx mean
    scores_kernel<<<dim3(8, 8, B_*NH_), 256>>>(mask);
    rowstats_kernel<<<B_*NH_*S_, 256>>>();
    colsum_kernel<<<B_*NH_, 256>>>();
    ctxmean_kernel<<<B_*NH_, 192>>>();

    // 3) embedding / e1 / e2 / implicit classifiers
    idx_kernel<<<B_, 256>>>(mask);
    embed_kernel<<<B_, 256>>>(mha_out_w, mha_out_b, asp_w, asp_b, opi_w, opi_b,
                              ia_w, ia_b, io_w, io_b, out);

    // 4) x passthrough output
    cudaMemcpyAsync(out + O_X, x, sizeof(float) * (size_t)BS_ * D_, cudaMemcpyDeviceToDevice);

    // 5) build se1/se2
    build_se_kernel<<<BS_, 256>>>(x);

    // 6) decoder stacks
    struct Stack {
        float* h; const float *iw, *ib, *ow, *ob, *g, *bt; size_t oSE;
    } stacks[2] = {
        { h1, fwd_iw, fwd_ib, fwd_ow, fwd_ob, fwd_g, fwd_bt, O_SE1 },
        { h2, rev_iw, rev_ib, rev_ow, rev_ob, rev_g, rev_bt, O_SE2 },
    };
    for (int s = 0; s < 2; s++) {
        Stack& st = stacks[s];
        for (int l = 0; l < NL_; l++) {
            sgemm_kernel<1><<<dim3(DFF_/128, BS_/128), 256>>>(
                st.h, D_, st.iw + (size_t)l*DFF_*D_, D_, inter, DFF_,
                st.ib + (size_t)l*DFF_, nullptr, D_);
            sgemm_kernel<2><<<dim3(D_/128, BS_/128), 256>>>(
                inter, DFF_, st.ow + (size_t)l*D_*DFF_, DFF_, tmp, D_,
                st.ob + (size_t)l*D_, st.h, DFF_);
            float* lnout = (l == NL_-1) ? (out + st.oSE) : st.h;
            ln_kernel<<<BS_, 256>>>(tmp, st.g + (size_t)l*D_, st.bt + (size_t)l*D_, lnout);
        }
    }

    // 7) classifier logits
    logits_kernel<<<BS_, 256>>>(out + O_SE1, cls_a_w, cls_a_b, out + O_LA);
    logits_kernel<<<BS_, 256>>>(out + O_SE2, cls_o_w, cls_o_b, out + O_LO);
}

// round 4
// speedup vs baseline: 1.6425x; 1.6425x over previous
#include <cuda_runtime.h>
#include <cuda_bf16.h>
#include <mma.h>
#include <math.h>
#include <stdint.h>

using namespace nvcuda;

#define B_   16
#define S_   1024
#define D_   768
#define NH_  4
#define HD_  192
#define DFF_ 3072
#define NL_  2
#define C_   3
#define BS_  (B_*S_)     // 16384
#define TD_  (3*D_)      // 2304

// ---- output layout (floats) ----
#define O_LA  ((size_t)0)
#define O_LO  ((size_t)49152)
#define O_X   ((size_t)98304)
#define O_SE1 ((size_t)12681216)
#define O_SE2 ((size_t)25264128)
#define O_IA  ((size_t)37847040)
#define O_IO  ((size_t)37847072)
#define O_E1  ((size_t)37847104)
#define O_E2  ((size_t)37859392)

// ---- scratch (device globals) ----
__device__ float g_qkv[(size_t)BS_*TD_];
__device__ float g_scores[(size_t)B_*NH_*S_*S_];
__device__ float g_m[B_*NH_*S_];
__device__ float g_z[B_*NH_*S_];
__device__ float g_w[B_*NH_*S_];
__device__ float g_ctxmean[B_*D_];
__device__ float g_e1[B_*D_];
__device__ float g_e2[B_*D_];
__device__ int   g_idx[B_];
__device__ float g_h1[(size_t)BS_*D_];
__device__ float g_h2[(size_t)BS_*D_];
__device__ float g_tmp[(size_t)BS_*D_];

// bf16 split operand buffers
__device__ __nv_bfloat16 g_ah[(size_t)BS_*D_];
__device__ __nv_bfloat16 g_al[(size_t)BS_*D_];
__device__ __nv_bfloat16 g_ih[(size_t)BS_*DFF_];
__device__ __nv_bfloat16 g_il[(size_t)BS_*DFF_];
__device__ __nv_bfloat16 g_bh[(size_t)DFF_*D_];
__device__ __nv_bfloat16 g_bl[(size_t)DFF_*D_];
__device__ __nv_bfloat16 g_qh[(size_t)B_*NH_*S_*HD_];
__device__ __nv_bfloat16 g_ql[(size_t)B_*NH_*S_*HD_];
__device__ __nv_bfloat16 g_kh[(size_t)B_*NH_*S_*HD_];
__device__ __nv_bfloat16 g_kl[(size_t)B_*NH_*S_*HD_];

// ============================================================
__device__ __forceinline__ uint32_t smem_u32(const void* p) {
    uint32_t a;
    asm("{ .reg .u64 t; cvta.to.shared.u64 t, %1; cvt.u32.u64 %0, t; }" : "=r"(a) : "l"(p));
    return a;
}
__device__ __forceinline__ void cp16(uint32_t dst, const void* src) {
    asm volatile("cp.async.cg.shared.global [%0], [%1], 16;" :: "r"(dst), "l"(src));
}
#define CP_COMMIT() asm volatile("cp.async.commit_group;" ::: "memory")
#define CP_WAIT0()  asm volatile("cp.async.wait_group 0;" ::: "memory")
#define CP_WAIT1()  asm volatile("cp.async.wait_group 1;" ::: "memory")

__device__ __forceinline__ void split_val(float v, __nv_bfloat16& h, __nv_bfloat16& l) {
    h = __float2bfloat16(v);
    l = __float2bfloat16(v - __bfloat162float(h));
}

// ============================================================
// Split-bf16 tensor-core GEMM via wmma (HMMA; baseline PTX, no "a" features).
// C[m,n] = sum_k (Ah+Al)[m,k]*(Bh+Bl)[n,k]   (3 products: hh, hl, lh)
// CTA tile 128x128, 8 warps in 4(M)x2(N), warp tile 32x64, K-chunk 32,
// cp.async double-buffered smem, accumulators staged via smem for epilogue.
// EPI: 0 = bias, fp32 C + pack Q/K bf16
//      1 = bias + exact GELU -> bf16 hi/lo (Ch/Cl)
//      2 = bias + residual -> fp32 C
//      3 = scale + mask -> fp32 C (batched, scores)
// ============================================================
// smem per stage: Ah|Al|Bh|Bl, each 128 rows x 48 bf16 (row stride 96B) = 12288B.
#define SROW   48
#define MATB   12288
#define STAGEB 49152
#define GSMEM  (2*STAGEB)

template<int EPI>
__global__ void __launch_bounds__(256, 1) tc_gemm(
    const __nv_bfloat16* __restrict__ Ah, const __nv_bfloat16* __restrict__ Al, long aBatch,
    const __nv_bfloat16* __restrict__ Bh, const __nv_bfloat16* __restrict__ Bl, long bBatch,
    float* __restrict__ C, int ldc, long cBatch,
    __nv_bfloat16* __restrict__ Ch, __nv_bfloat16* __restrict__ Cl,
    const float* __restrict__ bias, const float* __restrict__ resid,
    int K, const int* __restrict__ mask,
    __nv_bfloat16* __restrict__ qh, __nv_bfloat16* __restrict__ ql,
    __nv_bfloat16* __restrict__ kh, __nv_bfloat16* __restrict__ kl)
{
    extern __shared__ char smem[];
    __nv_bfloat16* sbf = (__nv_bfloat16*)smem;
    float* sf = (float*)smem;
    const uint32_t sb = smem_u32(smem);
    const int tid = threadIdx.x;
    const int wid = tid >> 5;
    const int wm = wid >> 1;       // 0..3
    const int wn = wid & 1;        // 0..1
    const int m0 = blockIdx.y * 128;
    const int n0 = blockIdx.x * 128;
    const int z  = blockIdx.z;

    Ah += (size_t)z * aBatch; Al += (size_t)z * aBatch;
    Bh += (size_t)z * bBatch; Bl += (size_t)z * bBatch;
    if (C) C += (size_t)z * cBatch;

    wmma::fragment<wmma::accumulator, 16, 16, 16, float> acc[2][4];
#pragma unroll
    for (int i = 0; i < 2; i++)
#pragma unroll
        for (int j = 0; j < 4; j++) wmma::fill_fragment(acc[i][j], 0.0f);

    const int nk = K >> 5;

    auto load_stage = [&](int st, int k0) {
        uint32_t base = sb + st * STAGEB;
#pragma unroll
        for (int v = tid; v < 512; v += 256) {
            int r = v >> 2, cg = v & 3;
            uint32_t so = r * 96 + cg * 16;
            size_t ga = (size_t)(m0 + r) * K + k0 + cg * 8;
            size_t gb = (size_t)(n0 + r) * K + k0 + cg * 8;
            cp16(base + so,            Ah + ga);
            cp16(base + MATB + so,     Al + ga);
            cp16(base + 2*MATB + so,   Bh + gb);
            cp16(base + 3*MATB + so,   Bl + gb);
        }
    };

    load_stage(0, 0);
    CP_COMMIT();

    for (int c = 0; c < nk; c++) {
        const int st = c & 1;
        if (c + 1 < nk) {
            load_stage(st ^ 1, (c + 1) << 5);
            CP_COMMIT();
            CP_WAIT1();
        } else {
            CP_WAIT0();
        }
        __syncthreads();

        const __nv_bfloat16* As_h = sbf + st * (STAGEB/2);
        const __nv_bfloat16* As_l = As_h + MATB/2;
        const __nv_bfloat16* Bs_h = As_h + MATB;
        const __nv_bfloat16* Bs_l = As_h + 3*(MATB/2);

#pragma unroll
        for (int kst = 0; kst < 2; kst++) {
            wmma::fragment<wmma::matrix_a, 16, 16, 16, __nv_bfloat16, wmma::row_major> fah[2], fal[2];
            wmma::fragment<wmma::matrix_b, 16, 16, 16, __nv_bfloat16, wmma::col_major> fbh[4], fbl[4];
#pragma unroll
            for (int i = 0; i < 2; i++) {
                const int rr = wm * 32 + i * 16;
                wmma::load_matrix_sync(fah[i], As_h + rr * SROW + kst * 16, SROW);
                wmma::load_matrix_sync(fal[i], As_l + rr * SROW + kst * 16, SROW);
            }
#pragma unroll
            for (int j = 0; j < 4; j++) {
                const int rr = wn * 64 + j * 16;
                wmma::load_matrix_sync(fbh[j], Bs_h + rr * SROW + kst * 16, SROW);
                wmma::load_matrix_sync(fbl[j], Bs_l + rr * SROW + kst * 16, SROW);
            }
#pragma unroll
            for (int i = 0; i < 2; i++)
#pragma unroll
                for (int j = 0; j < 4; j++) {
                    wmma::mma_sync(acc[i][j], fah[i], fbh[j], acc[i][j]);
                    wmma::mma_sync(acc[i][j], fah[i], fbl[j], acc[i][j]);
                    wmma::mma_sync(acc[i][j], fal[i], fbh[j], acc[i][j]);
                }
        }
        __syncthreads();
    }

    // stage accumulators to smem (reuse operand buffers)
#pragma unroll
    for (int i = 0; i < 2; i++)
#pragma unroll
        for (int j = 0; j < 4; j++)
            wmma::store_matrix_sync(sf + (wm*32 + i*16) * 128 + wn*64 + j*16,
                                    acc[i][j], 128, wmma::mem_row_major);
    __syncthreads();

    // ---- epilogue: 64 elements per thread, coalesced over columns ----
#pragma unroll 4
    for (int it = 0; it < 64; it++) {
        const int idx = it * 256 + tid;
        const int r = idx >> 7;
        const int cc = idx & 127;
        const int row = m0 + r;
        const int col = n0 + cc;
        float v = sf[idx];
        if (EPI == 0) {
            v += bias[col];
            C[(size_t)row * ldc + col] = v;
            if (col < 2 * D_) {
                int b_ = row >> 10, s_ = row & 1023;
                int c2 = (col < D_) ? col : (col - D_);
                int zz = b_ * NH_ + c2 / HD_;
                size_t po = (size_t)zz * (S_*HD_) + (size_t)s_ * HD_ + (c2 % HD_);
                __nv_bfloat16 h, l; split_val(v, h, l);
                if (col < D_) { qh[po] = h; ql[po] = l; }
                else          { kh[po] = h; kl[po] = l; }
            }
        } else if (EPI == 1) {
            v += bias[col];
            v = 0.5f * v * (1.0f + erff(v * 0.70710678118654752f));
            __nv_bfloat16 h, l; split_val(v, h, l);
            Ch[(size_t)row * ldc + col] = h;
            Cl[(size_t)row * ldc + col] = l;
        } else if (EPI == 2) {
            v += bias[col] + resid[(size_t)row * ldc + col];
            C[(size_t)row * ldc + col] = v;
        } else {
            v *= 0.07216878364870322f;  // 1/sqrt(192)
            const int b_ = z >> 2;
            if (mask[b_ * S_ + col] == 0) v = -1e30f;
            C[(size_t)row * ldc + col] = v;
        }
    }
}

// ============================================================
// split fp32 -> bf16 hi/lo
__global__ void split_kernel(const float* __restrict__ in,
                             __nv_bfloat16* __restrict__ hi, __nv_bfloat16* __restrict__ lo,
                             size_t n)
{
    size_t i = ((size_t)blockIdx.x * blockDim.x + threadIdx.x) * 4;
    if (i >= n) return;
    float4 v = *(const float4*)(in + i);
    __nv_bfloat16 h0,l0,h1,l1,h2,l2,h3,l3;
    split_val(v.x,h0,l0); split_val(v.y,h1,l1); split_val(v.z,h2,l2); split_val(v.w,h3,l3);
    hi[i]=h0; hi[i+1]=h1; hi[i+2]=h2; hi[i+3]=h3;
    lo[i]=l0; lo[i+1]=l1; lo[i+2]=l2; lo[i+3]=l3;
}

// row max + exp-sum per score row
__global__ void rowstats_kernel()
{
    const int row = blockIdx.x;
    const int tid = threadIdx.x;
    const float* r = g_scores + (size_t)row * S_;
    float v0 = r[tid], v1 = r[tid+256], v2 = r[tid+512], v3 = r[tid+768];
    __shared__ float red[256];
    float mx = fmaxf(fmaxf(v0, v1), fmaxf(v2, v3));
    red[tid] = mx; __syncthreads();
    for (int st = 128; st > 0; st >>= 1) { if (tid < st) red[tid] = fmaxf(red[tid], red[tid+st]); __syncthreads(); }
    float m = red[0];
    __syncthreads();
    float se = __expf(v0 - m) + __expf(v1 - m) + __expf(v2 - m) + __expf(v3 - m);
    red[tid] = se; __syncthreads();
    for (int st = 128; st > 0; st >>= 1) { if (tid < st) red[tid] += red[tid+st]; __syncthreads(); }
    if (tid == 0) { g_m[row] = m; g_z[row] = red[0]; }
}

// w[z,k] = sum_q exp(s[q,k]-m_q)/z_q  — grid (64,4) x 256 threads
__global__ void colsum_kernel()
{
    const int zz = blockIdx.x;
    const int col = blockIdx.y * 256 + threadIdx.x;
    __shared__ float sm[S_], sz[S_];
    for (int q = threadIdx.x; q < S_; q += 256) { sm[q] = g_m[zz*S_+q]; sz[q] = 1.0f / g_z[zz*S_+q]; }
    __syncthreads();
    float acc = 0.f;
    const float* sc = g_scores + (size_t)zz * S_ * S_ + col;
    for (int q = 0; q < S_; q++) acc += __expf(sc[(size_t)q * S_] - sm[q]) * sz[q];
    g_w[zz*S_ + col] = acc;
}

__global__ void ctxmean_kernel()
{
    const int z = blockIdx.x;
    const int b = z >> 2, h = z & 3;
    const int d = threadIdx.x;
    __shared__ float w[S_];
    for (int k = d; k < S_; k += 192) w[k] = g_w[z*S_+k];
    __syncthreads();
    float acc = 0.f;
    const float* vb = g_qkv + (size_t)b * S_ * TD_ + 2*D_ + h*HD_ + d;
    for (int k = 0; k < S_; k++) acc += w[k] * vb[(size_t)k * TD_];
    g_ctxmean[b*D_ + h*HD_ + d] = acc * (1.0f / S_);
}

__global__ void idx_kernel(const int* __restrict__ mask)
{
    const int b = blockIdx.x, tid = threadIdx.x;
    __shared__ int red[256];
    int s = 0;
    for (int k = tid; k < S_; k += 256) s += mask[b*S_ + k];
    red[tid] = s; __syncthreads();
    for (int st = 128; st > 0; st >>= 1) { if (tid < st) red[tid] += red[tid+st]; __syncthreads(); }
    if (tid == 0) g_idx[b] = red[0] - 1;
}

__global__ void embed_kernel(
    const float* __restrict__ Wout, const float* __restrict__ bout,
    const float* __restrict__ Wasp, const float* __restrict__ basp,
    const float* __restrict__ Wopi, const float* __restrict__ bopi,
    const float* __restrict__ Wia,  const float* __restrict__ bia,
    const float* __restrict__ Wio,  const float* __restrict__ bio,
    float* __restrict__ out)
{
    const int b = blockIdx.x, tid = threadIdx.x;
    __shared__ float cm[D_], emb[D_], e1s[D_], e2s[D_];
    for (int d = tid; d < D_; d += 256) cm[d] = g_ctxmean[b*D_ + d];
    __syncthreads();
    for (int n = tid; n < D_; n += 256) {
        float a = bout[n];
        const float* wr = Wout + (size_t)n * D_;
        for (int d = 0; d < D_; d++) a += cm[d] * wr[d];
        emb[n] = a;
    }
    __syncthreads();
    for (int n = tid; n < D_; n += 256) {
        float a = basp[n], o = bopi[n];
        const float* wa = Wasp + (size_t)n * D_;
        const float* wo = Wopi + (size_t)n * D_;
        for (int d = 0; d < D_; d++) { a += emb[d] * wa[d]; o += emb[d] * wo[d]; }
        e1s[n] = a; e2s[n] = o;
    }
    __syncthreads();
    for (int d = tid; d < D_; d += 256) {
        g_e1[b*D_ + d] = e1s[d];
        g_e2[b*D_ + d] = e2s[d];
        out[O_E1 + (size_t)b*D_ + d] = e1s[d];
        out[O_E2 + (size_t)b*D_ + d] = e2s[d];
    }
    if (tid < 2) {
        float a = bia[tid];
        const float* w = Wia + (size_t)tid * D_;
        for (int d = 0; d < D_; d++) a += e1s[d] * w[d];
        out[O_IA + b*2 + tid] = a;
    } else if (tid < 4) {
        int c = tid - 2;
        float a = bio[c];
        const float* w = Wio + (size_t)c * D_;
        for (int d = 0; d < D_; d++) a += e2s[d] * w[d];
        out[O_IO + b*2 + c] = a;
    }
}

__global__ void build_se_kernel(const float* __restrict__ x)
{
    const int blk = blockIdx.x;
    const int b = blk >> 10, s = blk & 1023;
    const int idx = g_idx[b];
#pragma unroll
    for (int i = 0; i < 3; i++) {
        int d = threadIdx.x + i * 256;
        float xv = x[(size_t)blk * D_ + d];
        float e1v = g_e1[b*D_ + d], e2v = g_e2[b*D_ + d];
        float v1 = (s == idx) ? e2v : ((s == 0) ? e1v : xv);
        float v2 = (s == 0) ? e1v : ((s == idx) ? e2v : xv);
        g_h1[(size_t)blk * D_ + d] = v1;
        g_h2[(size_t)blk * D_ + d] = v2;
    }
}

// layernorm: fp32 out + bf16 hi/lo out for next GEMM A
__global__ void ln_kernel(const float* __restrict__ in,
                          const float* __restrict__ g, const float* __restrict__ bt,
                          float* __restrict__ outp,
                          __nv_bfloat16* __restrict__ oh, __nv_bfloat16* __restrict__ ol)
{
    const int row = blockIdx.x, tid = threadIdx.x;
    const float* r = in + (size_t)row * D_;
    float v0 = r[tid], v1 = r[tid+256], v2 = r[tid+512];
    __shared__ float red[256];
    red[tid] = v0 + v1 + v2; __syncthreads();
    for (int st = 128; st > 0; st >>= 1) { if (tid < st) red[tid] += red[tid+st]; __syncthreads(); }
    float mean = red[0] * (1.0f / D_);
    __syncthreads();
    float d0 = v0 - mean, d1 = v1 - mean, d2 = v2 - mean;
    red[tid] = d0*d0 + d1*d1 + d2*d2; __syncthreads();
    for (int st = 128; st > 0; st >>= 1) { if (tid < st) red[tid] += red[tid+st]; __syncthreads(); }
    float rstd = rsqrtf(red[0] * (1.0f / D_) + 1e-12f);
    float o0 = d0 * rstd * g[tid]     + bt[tid];
    float o1 = d1 * rstd * g[tid+256] + bt[tid+256];
    float o2 = d2 * rstd * g[tid+512] + bt[tid+512];
    float* o = outp + (size_t)row * D_;
    o[tid] = o0; o[tid+256] = o1; o[tid+512] = o2;
    __nv_bfloat16 h, l;
    size_t base = (size_t)row * D_;
    split_val(o0, h, l); oh[base+tid]     = h; ol[base+tid]     = l;
    split_val(o1, h, l); oh[base+tid+256] = h; ol[base+tid+256] = l;
    split_val(o2, h, l); oh[base+tid+512] = h; ol[base+tid+512] = l;
}

__global__ void logits_kernel(const float* __restrict__ in, const float* __restrict__ W,
                              const float* __restrict__ bias, float* __restrict__ outp)
{
    const int row = blockIdx.x, tid = threadIdx.x;
    __shared__ float srow[D_];
    const float* r = in + (size_t)row * D_;
    srow[tid] = r[tid]; srow[tid+256] = r[tid+256]; srow[tid+512] = r[tid+512];
    __syncthreads();
    float a0 = 0.f, a1 = 0.f, a2 = 0.f;
    for (int d = tid; d < D_; d += 256) {
        float x = srow[d];
        a0 += x * W[d]; a1 += x * W[D_ + d]; a2 += x * W[2*D_ + d];
    }
    __shared__ float red[3][256];
    red[0][tid] = a0; red[1][tid] = a1; red[2][tid] = a2;
    __syncthreads();
    for (int st = 128; st > 0; st >>= 1) {
        if (tid < st) {
            red[0][tid] += red[0][tid+st];
            red[1][tid] += red[1][tid+st];
            red[2][tid] += red[2][tid+st];
        }
        __syncthreads();
    }
    if (tid < 3) outp[(size_t)row * C_ + tid] = red[tid][0] + bias[tid];
}

// ============================================================
extern "C" void kernel_launch(void* const* d_in, const int* in_sizes, int n_in,
                              void* d_out, int out_size)
{
    const float* x        = (const float*)d_in[0];
    const int*   mask     = (const int*)  d_in[1];
    const float* mha_in_w = (const float*)d_in[2];
    const float* mha_in_b = (const float*)d_in[3];
    const float* mha_out_w= (const float*)d_in[4];
    const float* mha_out_b= (const float*)d_in[5];
    const float* asp_w    = (const float*)d_in[6];
    const float* asp_b    = (const float*)d_in[7];
    const float* opi_w    = (const float*)d_in[8];
    const float* opi_b    = (const float*)d_in[9];
    const float* ia_w     = (const float*)d_in[10];
    const float* ia_b     = (const float*)d_in[11];
    const float* io_w     = (const float*)d_in[12];
    const float* io_b     = (const float*)d_in[13];
    const float* fwd_iw   = (const float*)d_in[14];
    const float* fwd_ib   = (const float*)d_in[15];
    const float* fwd_ow   = (const float*)d_in[16];
    const float* fwd_ob   = (const float*)d_in[17];
    const float* fwd_g    = (const float*)d_in[18];
    const float* fwd_bt   = (const float*)d_in[19];
    const float* rev_iw   = (const float*)d_in[20];
    const float* rev_ib   = (const float*)d_in[21];
    const float* rev_ow   = (const float*)d_in[22];
    const float* rev_ob   = (const float*)d_in[23];
    const float* rev_g    = (const float*)d_in[24];
    const float* rev_bt   = (const float*)d_in[25];
    const float* cls_a_w  = (const float*)d_in[26];
    const float* cls_a_b  = (const float*)d_in[27];
    const float* cls_o_w  = (const float*)d_in[28];
    const float* cls_o_b  = (const float*)d_in[29];
    float* out = (float*)d_out;

    float *qkvp, *h1, *h2, *tmp, *scoresp;
    __nv_bfloat16 *ah, *al, *ih, *il, *bh, *bl, *qh, *ql, *kh, *kl;
    cudaGetSymbolAddress((void**)&qkvp,    g_qkv);
    cudaGetSymbolAddress((void**)&scoresp, g_scores);
    cudaGetSymbolAddress((void**)&h1,   g_h1);
    cudaGetSymbolAddress((void**)&h2,   g_h2);
    cudaGetSymbolAddress((void**)&tmp,  g_tmp);
    cudaGetSymbolAddress((void**)&ah,   g_ah);
    cudaGetSymbolAddress((void**)&al,   g_al);
    cudaGetSymbolAddress((void**)&ih,   g_ih);
    cudaGetSymbolAddress((void**)&il,   g_il);
    cudaGetSymbolAddress((void**)&bh,   g_bh);
    cudaGetSymbolAddress((void**)&bl,   g_bl);
    cudaGetSymbolAddress((void**)&qh,   g_qh);
    cudaGetSymbolAddress((void**)&ql,   g_ql);
    cudaGetSymbolAddress((void**)&kh,   g_kh);
    cudaGetSymbolAddress((void**)&kl,   g_kl);

    cudaFuncSetAttribute(tc_gemm<0>, cudaFuncAttributeMaxDynamicSharedMemorySize, GSMEM);
    cudaFuncSetAttribute(tc_gemm<1>, cudaFuncAttributeMaxDynamicSharedMemorySize, GSMEM);
    cudaFuncSetAttribute(tc_gemm<2>, cudaFuncAttributeMaxDynamicSharedMemorySize, GSMEM);
    cudaFuncSetAttribute(tc_gemm<3>, cudaFuncAttributeMaxDynamicSharedMemorySize, GSMEM);

    auto splits = [&](const float* src, __nv_bfloat16* h, __nv_bfloat16* l, size_t n) {
        split_kernel<<<(unsigned)((n/4 + 255) / 256), 256>>>(src, h, l, n);
    };

    // 1) QKV projection; epilogue packs Q/K bf16 hi/lo per head
    splits(x, ah, al, (size_t)BS_ * D_);
    splits(mha_in_w, bh, bl, (size_t)TD_ * D_);
    tc_gemm<0><<<dim3(TD_/128, BS_/128, 1), 256, GSMEM>>>(
        ah, al, 0, bh, bl, 0, qkvp, TD_, 0, nullptr, nullptr,
        mha_in_b, nullptr, D_, nullptr, qh, ql, kh, kl);

    // 2) attention scores (batched over 64 z) + softmax stats + colsum + ctx mean
    tc_gemm<3><<<dim3(S_/128, S_/128, B_*NH_), 256, GSMEM>>>(
        qh, ql, (long)S_*HD_, kh, kl, (long)S_*HD_, scoresp, S_, (long)S_*S_,
        nullptr, nullptr, nullptr, nullptr, HD_, mask, nullptr, nullptr, nullptr, nullptr);
    rowstats_kernel<<<B_*NH_*S_, 256>>>();
    colsum_kernel<<<dim3(B_*NH_, 4), 256>>>();
    ctxmean_kernel<<<B_*NH_, 192>>>();

    // 3) embedding path
    idx_kernel<<<B_, 256>>>(mask);
    embed_kernel<<<B_, 256>>>(mha_out_w, mha_out_b, asp_w, asp_b, opi_w, opi_b,
                              ia_w, ia_b, io_w, io_b, out);

    // 4) x passthrough
    cudaMemcpyAsync(out + O_X, x, sizeof(float) * (size_t)BS_ * D_, cudaMemcpyDeviceToDevice);

    // 5) build se1/se2
    build_se_kernel<<<BS_, 256>>>(x);

    // 6) decoder stacks on tensor cores
    struct Stack { float* h; const float *iw, *ib, *ow, *ob, *g, *bt; size_t oSE; }
    stacks[2] = {
        { h1, fwd_iw, fwd_ib, fwd_ow, fwd_ob, fwd_g, fwd_bt, O_SE1 },
        { h2, rev_iw, rev_ib, rev_ow, rev_ob, rev_g, rev_bt, O_SE2 },
    };
    for (int s = 0; s < 2; s++) {
        Stack& st = stacks[s];
        splits(st.h, ah, al, (size_t)BS_ * D_);
        for (int l = 0; l < NL_; l++) {
            splits(st.iw + (size_t)l*DFF_*D_, bh, bl, (size_t)DFF_*D_);
            tc_gemm<1><<<dim3(DFF_/128, BS_/128, 1), 256, GSMEM>>>(
                ah, al, 0, bh, bl, 0, nullptr, DFF_, 0, ih, il,
                st.ib + (size_t)l*DFF_, nullptr, D_, nullptr, nullptr, nullptr, nullptr, nullptr);
            splits(st.ow + (size_t)l*D_*DFF_, bh, bl, (size_t)D_*DFF_);
            tc_gemm<2><<<dim3(D_/128, BS_/128, 1), 256, GSMEM>>>(
                ih, il, 0, bh, bl, 0, tmp, D_, 0, nullptr, nullptr,
                st.ob + (size_t)l*D_, st.h, DFF_, nullptr, nullptr, nullptr, nullptr, nullptr);
            float* lnout = (l == NL_-1) ? (out + st.oSE) : st.h;
            ln_kernel<<<BS_, 256>>>(tmp, st.g + (size_t)l*D_, st.bt + (size_t)l*D_, lnout, ah, al);
        }
    }

    // 7) classifier logits
    logits_kernel<<<BS_, 256>>>(out + O_SE1, cls_a_w, cls_a_b, out + O_LA);
    logits_kernel<<<BS_, 256>>>(out + O_SE2, cls_o_w, cls_o_b, out + O_LO);
}

// round 5
// speedup vs baseline: 2.2920x; 1.3954x over previous
#include <cuda_runtime.h>
#include <cuda_bf16.h>
#include <mma.h>
#include <math.h>
#include <stdint.h>

using namespace nvcuda;

#define B_   16
#define S_   1024
#define D_   768
#define NH_  4
#define HD_  192
#define DFF_ 3072
#define NL_  2
#define C_   3
#define BS_  (B_*S_)     // 16384
#define TD_  (3*D_)      // 2304

// ---- output layout (floats) ----
#define O_LA  ((size_t)0)
#define O_LO  ((size_t)49152)
#define O_X   ((size_t)98304)
#define O_SE1 ((size_t)12681216)
#define O_SE2 ((size_t)25264128)
#define O_IA  ((size_t)37847040)
#define O_IO  ((size_t)37847072)
#define O_E1  ((size_t)37847104)
#define O_E2  ((size_t)37859392)

// ---- scratch (device globals) ----
__device__ float g_qkv[(size_t)BS_*TD_];
__device__ float g_scores[(size_t)B_*NH_*S_*S_];
__device__ float g_m[B_*NH_*S_];
__device__ float g_z[B_*NH_*S_];
__device__ float g_w[B_*NH_*S_];
__device__ float g_ctxmean[B_*D_];
__device__ float g_e1[B_*D_];
__device__ float g_e2[B_*D_];
__device__ int   g_idx[B_];
__device__ float g_h1[(size_t)BS_*D_];
__device__ float g_h2[(size_t)BS_*D_];
__device__ float g_tmp[(size_t)BS_*D_];

// bf16 split operand buffers
__device__ __nv_bfloat16 g_ah[(size_t)BS_*D_];
__device__ __nv_bfloat16 g_al[(size_t)BS_*D_];
__device__ __nv_bfloat16 g_ih[(size_t)BS_*DFF_];
__device__ __nv_bfloat16 g_il[(size_t)BS_*DFF_];
__device__ __nv_bfloat16 g_bh[(size_t)DFF_*D_];
__device__ __nv_bfloat16 g_bl[(size_t)DFF_*D_];
__device__ __nv_bfloat16 g_qh[(size_t)B_*NH_*S_*HD_];
__device__ __nv_bfloat16 g_ql[(size_t)B_*NH_*S_*HD_];
__device__ __nv_bfloat16 g_kh[(size_t)B_*NH_*S_*HD_];
__device__ __nv_bfloat16 g_kl[(size_t)B_*NH_*S_*HD_];

// ============================================================
__device__ __forceinline__ uint32_t smem_u32(const void* p) {
    uint32_t a;
    asm("{ .reg .u64 t; cvta.to.shared.u64 t, %1; cvt.u32.u64 %0, t; }" : "=r"(a) : "l"(p));
    return a;
}
__device__ __forceinline__ void cp16(uint32_t dst, const void* src) {
    asm volatile("cp.async.cg.shared.global [%0], [%1], 16;" :: "r"(dst), "l"(src));
}
#define CP_COMMIT() asm volatile("cp.async.commit_group;" ::: "memory")
#define CP_WAIT0()  asm volatile("cp.async.wait_group 0;" ::: "memory")
#define CP_WAIT1()  asm volatile("cp.async.wait_group 1;" ::: "memory")

__device__ __forceinline__ void split_val(float v, __nv_bfloat16& h, __nv_bfloat16& l) {
    h = __float2bfloat16(v);
    l = __float2bfloat16(v - __bfloat162float(h));
}

// ============================================================
// Split-bf16 tensor-core GEMM via wmma (HMMA; baseline PTX).
// C[m,n] = sum_k (Ah+Al)[m,k]*(Bh+Bl)[n,k]   (3 products: hh, hl, lh)
// CTA tile 128x128, 8 warps in 4(M)x2(N), warp tile 32x64, K-chunk 32,
// cp.async double-buffered smem. __launch_bounds__(256,2) -> 2 CTAs/SM.
// B fragments loaded inside j-loop to keep register liveness low.
// EPI: 0 = bias, fp32 C + pack Q/K bf16
//      1 = bias + exact GELU -> bf16 hi/lo (Ch/Cl)
//      2 = bias + residual -> fp32 C
//      3 = scale + mask -> fp32 C (batched, scores)
// ============================================================
// smem per stage: Ah|Al|Bh|Bl, each 128 rows x 48 bf16 (row stride 96B) = 12288B.
#define SROW   48
#define MATB   12288
#define STAGEB 49152
#define GSMEM  (2*STAGEB)

template<int EPI>
__global__ void __launch_bounds__(256, 2) tc_gemm(
    const __nv_bfloat16* __restrict__ Ah, const __nv_bfloat16* __restrict__ Al, long aBatch,
    const __nv_bfloat16* __restrict__ Bh, const __nv_bfloat16* __restrict__ Bl, long bBatch,
    float* __restrict__ C, int ldc, long cBatch,
    __nv_bfloat16* __restrict__ Ch, __nv_bfloat16* __restrict__ Cl,
    const float* __restrict__ bias, const float* __restrict__ resid,
    int K, const int* __restrict__ mask,
    __nv_bfloat16* __restrict__ qh, __nv_bfloat16* __restrict__ ql,
    __nv_bfloat16* __restrict__ kh, __nv_bfloat16* __restrict__ kl)
{
    extern __shared__ char smem[];
    __nv_bfloat16* sbf = (__nv_bfloat16*)smem;
    float* sf = (float*)smem;
    const uint32_t sb = smem_u32(smem);
    const int tid = threadIdx.x;
    const int wid = tid >> 5;
    const int wm = wid >> 1;       // 0..3
    const int wn = wid & 1;        // 0..1
    const int m0 = blockIdx.y * 128;
    const int n0 = blockIdx.x * 128;
    const int z  = blockIdx.z;

    Ah += (size_t)z * aBatch; Al += (size_t)z * aBatch;
    Bh += (size_t)z * bBatch; Bl += (size_t)z * bBatch;
    if (C) C += (size_t)z * cBatch;

    wmma::fragment<wmma::accumulator, 16, 16, 16, float> acc[2][4];
#pragma unroll
    for (int i = 0; i < 2; i++)
#pragma unroll
        for (int j = 0; j < 4; j++) wmma::fill_fragment(acc[i][j], 0.0f);

    const int nk = K >> 5;

    auto load_stage = [&](int st, int k0) {
        uint32_t base = sb + st * STAGEB;
#pragma unroll
        for (int v = tid; v < 512; v += 256) {
            int r = v >> 2, cg = v & 3;
            uint32_t so = r * 96 + cg * 16;
            size_t ga = (size_t)(m0 + r) * K + k0 + cg * 8;
            size_t gb = (size_t)(n0 + r) * K + k0 + cg * 8;
            cp16(base + so,            Ah + ga);
            cp16(base + MATB + so,     Al + ga);
            cp16(base + 2*MATB + so,   Bh + gb);
            cp16(base + 3*MATB + so,   Bl + gb);
        }
    };

    load_stage(0, 0);
    CP_COMMIT();

    for (int c = 0; c < nk; c++) {
        const int st = c & 1;
        if (c + 1 < nk) {
            load_stage(st ^ 1, (c + 1) << 5);
            CP_COMMIT();
            CP_WAIT1();
        } else {
            CP_WAIT0();
        }
        __syncthreads();

        const __nv_bfloat16* As_h = sbf + st * (STAGEB/2);
        const __nv_bfloat16* As_l = As_h + MATB/2;
        const __nv_bfloat16* Bs_h = As_h + MATB;
        const __nv_bfloat16* Bs_l = As_h + 3*(MATB/2);

#pragma unroll
        for (int kst = 0; kst < 2; kst++) {
            wmma::fragment<wmma::matrix_a, 16, 16, 16, __nv_bfloat16, wmma::row_major> fah[2], fal[2];
#pragma unroll
            for (int i = 0; i < 2; i++) {
                const int rr = wm * 32 + i * 16;
                wmma::load_matrix_sync(fah[i], As_h + rr * SROW + kst * 16, SROW);
                wmma::load_matrix_sync(fal[i], As_l + rr * SROW + kst * 16, SROW);
            }
#pragma unroll
            for (int j = 0; j < 4; j++) {
                wmma::fragment<wmma::matrix_b, 16, 16, 16, __nv_bfloat16, wmma::col_major> fbh, fbl;
                const int rr = wn * 64 + j * 16;
                wmma::load_matrix_sync(fbh, Bs_h + rr * SROW + kst * 16, SROW);
                wmma::load_matrix_sync(fbl, Bs_l + rr * SROW + kst * 16, SROW);
#pragma unroll
                for (int i = 0; i < 2; i++) {
                    wmma::mma_sync(acc[i][j], fah[i], fbh, acc[i][j]);
                    wmma::mma_sync(acc[i][j], fal[i], fbh, acc[i][j]);
                    wmma::mma_sync(acc[i][j], fah[i], fbl, acc[i][j]);
                }
            }
        }
        __syncthreads();
    }

    // stage accumulators to smem (reuse operand buffers)
#pragma unroll
    for (int i = 0; i < 2; i++)
#pragma unroll
        for (int j = 0; j < 4; j++)
            wmma::store_matrix_sync(sf + (wm*32 + i*16) * 128 + wn*64 + j*16,
                                    acc[i][j], 128, wmma::mem_row_major);
    __syncthreads();

    // ---- epilogue: 64 elements per thread, coalesced over columns ----
#pragma unroll 4
    for (int it = 0; it < 64; it++) {
        const int idx = it * 256 + tid;
        const int r = idx >> 7;
        const int cc = idx & 127;
        const int row = m0 + r;
        const int col = n0 + cc;
        float v = sf[idx];
        if (EPI == 0) {
            v += bias[col];
            C[(size_t)row * ldc + col] = v;
            if (col < 2 * D_) {
                int b_ = row >> 10, s_ = row & 1023;
                int c2 = (col < D_) ? col : (col - D_);
                int zz = b_ * NH_ + c2 / HD_;
                size_t po = (size_t)zz * (S_*HD_) + (size_t)s_ * HD_ + (c2 % HD_);
                __nv_bfloat16 h, l; split_val(v, h, l);
                if (col < D_) { qh[po] = h; ql[po] = l; }
                else          { kh[po] = h; kl[po] = l; }
            }
        } else if (EPI == 1) {
            v += bias[col];
            v = 0.5f * v * (1.0f + erff(v * 0.70710678118654752f));
            __nv_bfloat16 h, l; split_val(v, h, l);
            Ch[(size_t)row * ldc + col] = h;
            Cl[(size_t)row * ldc + col] = l;
        } else if (EPI == 2) {
            v += bias[col] + resid[(size_t)row * ldc + col];
            C[(size_t)row * ldc + col] = v;
        } else {
            v *= 0.07216878364870322f;  // 1/sqrt(192)
            const int b_ = z >> 2;
            if (mask[b_ * S_ + col] == 0) v = -1e30f;
            C[(size_t)row * ldc + col] = v;
        }
    }
}

// ============================================================
// split fp32 -> bf16 hi/lo
__global__ void split_kernel(const float* __restrict__ in,
                             __nv_bfloat16* __restrict__ hi, __nv_bfloat16* __restrict__ lo,
                             size_t n)
{
    size_t i = ((size_t)blockIdx.x * blockDim.x + threadIdx.x) * 4;
    if (i >= n) return;
    float4 v = *(const float4*)(in + i);
    __nv_bfloat16 h0,l0,h1,l1,h2,l2,h3,l3;
    split_val(v.x,h0,l0); split_val(v.y,h1,l1); split_val(v.z,h2,l2); split_val(v.w,h3,l3);
    hi[i]=h0; hi[i+1]=h1; hi[i+2]=h2; hi[i+3]=h3;
    lo[i]=l0; lo[i+1]=l1; lo[i+2]=l2; lo[i+3]=l3;
}

// row max + exp-sum per score row
__global__ void rowstats_kernel()
{
    const int row = blockIdx.x;
    const int tid = threadIdx.x;
    const float* r = g_scores + (size_t)row * S_;
    float v0 = r[tid], v1 = r[tid+256], v2 = r[tid+512], v3 = r[tid+768];
    __shared__ float red[256];
    float mx = fmaxf(fmaxf(v0, v1), fmaxf(v2, v3));
    red[tid] = mx; __syncthreads();
    for (int st = 128; st > 0; st >>= 1) { if (tid < st) red[tid] = fmaxf(red[tid], red[tid+st]); __syncthreads(); }
    float m = red[0];
    __syncthreads();
    float se = __expf(v0 - m) + __expf(v1 - m) + __expf(v2 - m) + __expf(v3 - m);
    red[tid] = se; __syncthreads();
    for (int st = 128; st > 0; st >>= 1) { if (tid < st) red[tid] += red[tid+st]; __syncthreads(); }
    if (tid == 0) { g_m[row] = m; g_z[row] = red[0]; }
}

// w[z,k] = sum_q exp(s[q,k]-m_q)/z_q  — grid (64,4) x 256 threads
__global__ void colsum_kernel()
{
    const int zz = blockIdx.x;
    const int col = blockIdx.y * 256 + threadIdx.x;
    __shared__ float sm[S_], sz[S_];
    for (int q = threadIdx.x; q < S_; q += 256) { sm[q] = g_m[zz*S_+q]; sz[q] = 1.0f / g_z[zz*S_+q]; }
    __syncthreads();
    float acc = 0.f;
    const float* sc = g_scores + (size_t)zz * S_ * S_ + col;
    for (int q = 0; q < S_; q++) acc += __expf(sc[(size_t)q * S_] - sm[q]) * sz[q];
    g_w[zz*S_ + col] = acc;
}

__global__ void ctxmean_kernel()
{
    const int z = blockIdx.x;
    const int b = z >> 2, h = z & 3;
    const int d = threadIdx.x;
    __shared__ float w[S_];
    for (int k = d; k < S_; k += 192) w[k] = g_w[z*S_+k];
    __syncthreads();
    float acc = 0.f;
    const float* vb = g_qkv + (size_t)b * S_ * TD_ + 2*D_ + h*HD_ + d;
    for (int k = 0; k < S_; k++) acc += w[k] * vb[(size_t)k * TD_];
    g_ctxmean[b*D_ + h*HD_ + d] = acc * (1.0f / S_);
}

__global__ void idx_kernel(const int* __restrict__ mask)
{
    const int b = blockIdx.x, tid = threadIdx.x;
    __shared__ int red[256];
    int s = 0;
    for (int k = tid; k < S_; k += 256) s += mask[b*S_ + k];
    red[tid] = s; __syncthreads();
    for (int st = 128; st > 0; st >>= 1) { if (tid < st) red[tid] += red[tid+st]; __syncthreads(); }
    if (tid == 0) g_idx[b] = red[0] - 1;
}

__global__ void embed_kernel(
    const float* __restrict__ Wout, const float* __restrict__ bout,
    const float* __restrict__ Wasp, const float* __restrict__ basp,
    const float* __restrict__ Wopi, const float* __restrict__ bopi,
    const float* __restrict__ Wia,  const float* __restrict__ bia,
    const float* __restrict__ Wio,  const float* __restrict__ bio,
    float* __restrict__ out)
{
    const int b = blockIdx.x, tid = threadIdx.x;
    __shared__ float cm[D_], emb[D_], e1s[D_], e2s[D_];
    for (int d = tid; d < D_; d += 256) cm[d] = g_ctxmean[b*D_ + d];
    __syncthreads();
    for (int n = tid; n < D_; n += 256) {
        float a = bout[n];
        const float* wr = Wout + (size_t)n * D_;
        for (int d = 0; d < D_; d++) a += cm[d] * wr[d];
        emb[n] = a;
    }
    __syncthreads();
    for (int n = tid; n < D_; n += 256) {
        float a = basp[n], o = bopi[n];
        const float* wa = Wasp + (size_t)n * D_;
        const float* wo = Wopi + (size_t)n * D_;
        for (int d = 0; d < D_; d++) { a += emb[d] * wa[d]; o += emb[d] * wo[d]; }
        e1s[n] = a; e2s[n] = o;
    }
    __syncthreads();
    for (int d = tid; d < D_; d += 256) {
        g_e1[b*D_ + d] = e1s[d];
        g_e2[b*D_ + d] = e2s[d];
        out[O_E1 + (size_t)b*D_ + d] = e1s[d];
        out[O_E2 + (size_t)b*D_ + d] = e2s[d];
    }
    if (tid < 2) {
        float a = bia[tid];
        const float* w = Wia + (size_t)tid * D_;
        for (int d = 0; d < D_; d++) a += e1s[d] * w[d];
        out[O_IA + b*2 + tid] = a;
    } else if (tid < 4) {
        int c = tid - 2;
        float a = bio[c];
        const float* w = Wio + (size_t)c * D_;
        for (int d = 0; d < D_; d++) a += e2s[d] * w[d];
        out[O_IO + b*2 + c] = a;
    }
}

__global__ void build_se_kernel(const float* __restrict__ x)
{
    const int blk = blockIdx.x;
    const int b = blk >> 10, s = blk & 1023;
    const int idx = g_idx[b];
#pragma unroll
    for (int i = 0; i < 3; i++) {
        int d = threadIdx.x + i * 256;
        float xv = x[(size_t)blk * D_ + d];
        float e1v = g_e1[b*D_ + d], e2v = g_e2[b*D_ + d];
        float v1 = (s == idx) ? e2v : ((s == 0) ? e1v : xv);
        float v2 = (s == 0) ? e1v : ((s == idx) ? e2v : xv);
        g_h1[(size_t)blk * D_ + d] = v1;
        g_h2[(size_t)blk * D_ + d] = v2;
    }
}

// layernorm: fp32 out + bf16 hi/lo out for next GEMM A
__global__ void ln_kernel(const float* __restrict__ in,
                          const float* __restrict__ g, const float* __restrict__ bt,
                          float* __restrict__ outp,
                          __nv_bfloat16* __restrict__ oh, __nv_bfloat16* __restrict__ ol)
{
    const int row = blockIdx.x, tid = threadIdx.x;
    const float* r = in + (size_t)row * D_;
    float v0 = r[tid], v1 = r[tid+256], v2 = r[tid+512];
    __shared__ float red[256];
    red[tid] = v0 + v1 + v2; __syncthreads();
    for (int st = 128; st > 0; st >>= 1) { if (tid < st) red[tid] += red[tid+st]; __syncthreads(); }
    float mean = red[0] * (1.0f / D_);
    __syncthreads();
    float d0 = v0 - mean, d1 = v1 - mean, d2 = v2 - mean;
    red[tid] = d0*d0 + d1*d1 + d2*d2; __syncthreads();
    for (int st = 128; st > 0; st >>= 1) { if (tid < st) red[tid] += red[tid+st]; __syncthreads(); }
    float rstd = rsqrtf(red[0] * (1.0f / D_) + 1e-12f);
    float o0 = d0 * rstd * g[tid]     + bt[tid];
    float o1 = d1 * rstd * g[tid+256] + bt[tid+256];
    float o2 = d2 * rstd * g[tid+512] + bt[tid+512];
    float* o = outp + (size_t)row * D_;
    o[tid] = o0; o[tid+256] = o1; o[tid+512] = o2;
    __nv_bfloat16 h, l;
    size_t base = (size_t)row * D_;
    split_val(o0, h, l); oh[base+tid]     = h; ol[base+tid]     = l;
    split_val(o1, h, l); oh[base+tid+256] = h; ol[base+tid+256] = l;
    split_val(o2, h, l); oh[base+tid+512] = h; ol[base+tid+512] = l;
}

__global__ void logits_kernel(const float* __restrict__ in, const float* __restrict__ W,
                              const float* __restrict__ bias, float* __restrict__ outp)
{
    const int row = blockIdx.x, tid = threadIdx.x;
    __shared__ float srow[D_];
    const float* r = in + (size_t)row * D_;
    srow[tid] = r[tid]; srow[tid+256] = r[tid+256]; srow[tid+512] = r[tid+512];
    __syncthreads();
    float a0 = 0.f, a1 = 0.f, a2 = 0.f;
    for (int d = tid; d < D_; d += 256) {
        float x = srow[d];
        a0 += x * W[d]; a1 += x * W[D_ + d]; a2 += x * W[2*D_ + d];
    }
    __shared__ float red[3][256];
    red[0][tid] = a0; red[1][tid] = a1; red[2][tid] = a2;
    __syncthreads();
    for (int st = 128; st > 0; st >>= 1) {
        if (tid < st) {
            red[0][tid] += red[0][tid+st];
            red[1][tid] += red[1][tid+st];
            red[2][tid] += red[2][tid+st];
        }
        __syncthreads();
    }
    if (tid < 3) outp[(size_t)row * C_ + tid] = red[tid][0] + bias[tid];
}

// ============================================================
extern "C" void kernel_launch(void* const* d_in, const int* in_sizes, int n_in,
                              void* d_out, int out_size)
{
    const float* x        = (const float*)d_in[0];
    const int*   mask     = (const int*)  d_in[1];
    const float* mha_in_w = (const float*)d_in[2];
    const float* mha_in_b = (const float*)d_in[3];
    const float* mha_out_w= (const float*)d_in[4];
    const float* mha_out_b= (const float*)d_in[5];
    const float* asp_w    = (const float*)d_in[6];
    const float* asp_b    = (const float*)d_in[7];
    const float* opi_w    = (const float*)d_in[8];
    const float* opi_b    = (const float*)d_in[9];
    const float* ia_w     = (const float*)d_in[10];
    const float* ia_b     = (const float*)d_in[11];
    const float* io_w     = (const float*)d_in[12];
    const float* io_b     = (const float*)d_in[13];
    const float* fwd_iw   = (const float*)d_in[14];
    const float* fwd_ib   = (const float*)d_in[15];
    const float* fwd_ow   = (const float*)d_in[16];
    const float* fwd_ob   = (const float*)d_in[17];
    const float* fwd_g    = (const float*)d_in[18];
    const float* fwd_bt   = (const float*)d_in[19];
    const float* rev_iw   = (const float*)d_in[20];
    const float* rev_ib   = (const float*)d_in[21];
    const float* rev_ow   = (const float*)d_in[22];
    const float* rev_ob   = (const float*)d_in[23];
    const float* rev_g    = (const float*)d_in[24];
    const float* rev_bt   = (const float*)d_in[25];
    const float* cls_a_w  = (const float*)d_in[26];
    const float* cls_a_b  = (const float*)d_in[27];
    const float* cls_o_w  = (const float*)d_in[28];
    const float* cls_o_b  = (const float*)d_in[29];
    float* out = (float*)d_out;

    float *qkvp, *h1, *h2, *tmp, *scoresp;
    __nv_bfloat16 *ah, *al, *ih, *il, *bh, *bl, *qh, *ql, *kh, *kl;
    cudaGetSymbolAddress((void**)&qkvp,    g_qkv);
    cudaGetSymbolAddress((void**)&scoresp, g_scores);
    cudaGetSymbolAddress((void**)&h1,   g_h1);
    cudaGetSymbolAddress((void**)&h2,   g_h2);
    cudaGetSymbolAddress((void**)&tmp,  g_tmp);
    cudaGetSymbolAddress((void**)&ah,   g_ah);
    cudaGetSymbolAddress((void**)&al,   g_al);
    cudaGetSymbolAddress((void**)&ih,   g_ih);
    cudaGetSymbolAddress((void**)&il,   g_il);
    cudaGetSymbolAddress((void**)&bh,   g_bh);
    cudaGetSymbolAddress((void**)&bl,   g_bl);
    cudaGetSymbolAddress((void**)&qh,   g_qh);
    cudaGetSymbolAddress((void**)&ql,   g_ql);
    cudaGetSymbolAddress((void**)&kh,   g_kh);
    cudaGetSymbolAddress((void**)&kl,   g_kl);

    cudaFuncSetAttribute(tc_gemm<0>, cudaFuncAttributeMaxDynamicSharedMemorySize, GSMEM);
    cudaFuncSetAttribute(tc_gemm<1>, cudaFuncAttributeMaxDynamicSharedMemorySize, GSMEM);
    cudaFuncSetAttribute(tc_gemm<2>, cudaFuncAttributeMaxDynamicSharedMemorySize, GSMEM);
    cudaFuncSetAttribute(tc_gemm<3>, cudaFuncAttributeMaxDynamicSharedMemorySize, GSMEM);

    auto splits = [&](const float* src, __nv_bfloat16* h, __nv_bfloat16* l, size_t n) {
        split_kernel<<<(unsigned)((n/4 + 255) / 256), 256>>>(src, h, l, n);
    };

    // 1) QKV projection; epilogue packs Q/K bf16 hi/lo per head
    splits(x, ah, al, (size_t)BS_ * D_);
    splits(mha_in_w, bh, bl, (size_t)TD_ * D_);
    tc_gemm<0><<<dim3(TD_/128, BS_/128, 1), 256, GSMEM>>>(
        ah, al, 0, bh, bl, 0, qkvp, TD_, 0, nullptr, nullptr,
        mha_in_b, nullptr, D_, nullptr, qh, ql, kh, kl);

    // 2) attention scores (batched over 64 z) + softmax stats + colsum + ctx mean
    tc_gemm<3><<<dim3(S_/128, S_/128, B_*NH_), 256, GSMEM>>>(
        qh, ql, (long)S_*HD_, kh, kl, (long)S_*HD_, scoresp, S_, (long)S_*S_,
        nullptr, nullptr, nullptr, nullptr, HD_, mask, nullptr, nullptr, nullptr, nullptr);
    rowstats_kernel<<<B_*NH_*S_, 256>>>();
    colsum_kernel<<<dim3(B_*NH_, 4), 256>>>();
    ctxmean_kernel<<<B_*NH_, 192>>>();

    // 3) embedding path
    idx_kernel<<<B_, 256>>>(mask);
    embed_kernel<<<B_, 256>>>(mha_out_w, mha_out_b, asp_w, asp_b, opi_w, opi_b,
                              ia_w, ia_b, io_w, io_b, out);

    // 4) x passthrough
    cudaMemcpyAsync(out + O_X, x, sizeof(float) * (size_t)BS_ * D_, cudaMemcpyDeviceToDevice);

    // 5) build se1/se2
    build_se_kernel<<<BS_, 256>>>(x);

    // 6) decoder stacks on tensor cores
    struct Stack { float* h; const float *iw, *ib, *ow, *ob, *g, *bt; size_t oSE; }
    stacks[2] = {
        { h1, fwd_iw, fwd_ib, fwd_ow, fwd_ob, fwd_g, fwd_bt, O_SE1 },
        { h2, rev_iw, rev_ib, rev_ow, rev_ob, rev_g, rev_bt, O_SE2 },
    };
    for (int s = 0; s < 2; s++) {
        Stack& st = stacks[s];
        splits(st.h, ah, al, (size_t)BS_ * D_);
        for (int l = 0; l < NL_; l++) {
            splits(st.iw + (size_t)l*DFF_*D_, bh, bl, (size_t)DFF_*D_);
            tc_gemm<1><<<dim3(DFF_/128, BS_/128, 1), 256, GSMEM>>>(
                ah, al, 0, bh, bl, 0, nullptr, DFF_, 0, ih, il,
                st.ib + (size_t)l*DFF_, nullptr, D_, nullptr, nullptr, nullptr, nullptr, nullptr);
            splits(st.ow + (size_t)l*D_*DFF_, bh, bl, (size_t)D_*DFF_);
            tc_gemm<2><<<dim3(D_/128, BS_/128, 1), 256, GSMEM>>>(
                ih, il, 0, bh, bl, 0, tmp, D_, 0, nullptr, nullptr,
                st.ob + (size_t)l*D_, st.h, DFF_, nullptr, nullptr, nullptr, nullptr, nullptr);
            float* lnout = (l == NL_-1) ? (out + st.oSE) : st.h;
            ln_kernel<<<BS_, 256>>>(tmp, st.g + (size_t)l*D_, st.bt + (size_t)l*D_, lnout, ah, al);
        }
    }

    // 7) classifier logits
    logits_kernel<<<BS_, 256>>>(out + O_SE1, cls_a_w, cls_a_b, out + O_LA);
    logits_kernel<<<BS_, 256>>>(out + O_SE2, cls_o_w, cls_o_b, out + O_LO);
}

// round 7
// speedup vs baseline: 3.9232x; 1.7117x over previous
#include <cuda_runtime.h>
#include <cuda_fp16.h>
#include <mma.h>
#include <math.h>
#include <stdint.h>

using namespace nvcuda;

#define B_   16
#define S_   1024
#define D_   768
#define NH_  4
#define HD_  192
#define DFF_ 3072
#define NL_  2
#define C_   3
#define BS_  (B_*S_)     // 16384
#define TD_  (3*D_)      // 2304

// ---- output layout (floats) ----
#define O_LA  ((size_t)0)
#define O_LO  ((size_t)49152)
#define O_X   ((size_t)98304)
#define O_SE1 ((size_t)12681216)
#define O_SE2 ((size_t)25264128)
#define O_IA  ((size_t)37847040)
#define O_IO  ((size_t)37847072)
#define O_E1  ((size_t)37847104)
#define O_E2  ((size_t)37859392)

// ---- scratch (device globals) ----
__device__ float g_qkv[(size_t)BS_*TD_];
__device__ float g_scores[(size_t)B_*NH_*S_*S_];
__device__ float g_m[B_*NH_*S_];
__device__ float g_z[B_*NH_*S_];
__device__ float g_w[B_*NH_*S_];
__device__ float g_ctxmean[B_*D_];
__device__ float g_e1[B_*D_];
__device__ float g_e2[B_*D_];
__device__ int   g_idx[B_];
__device__ float g_h1[(size_t)BS_*D_];
__device__ float g_h2[(size_t)BS_*D_];
__device__ float g_tmp[(size_t)BS_*D_];

// fp16 operand buffers
__device__ __half g_ah[(size_t)BS_*D_];
__device__ __half g_ih[(size_t)BS_*DFF_];
__device__ __half g_bh[(size_t)DFF_*D_];
__device__ __half g_qh[(size_t)B_*NH_*S_*HD_];
__device__ __half g_kh[(size_t)B_*NH_*S_*HD_];

// ============================================================
__device__ __forceinline__ uint32_t smem_u32(const void* p) {
    uint32_t a;
    asm("{ .reg .u64 t; cvta.to.shared.u64 t, %1; cvt.u32.u64 %0, t; }" : "=r"(a) : "l"(p));
    return a;
}
__device__ __forceinline__ void cp16(uint32_t dst, const void* src) {
    asm volatile("cp.async.cg.shared.global [%0], [%1], 16;" :: "r"(dst), "l"(src));
}
#define CP_COMMIT() asm volatile("cp.async.commit_group;" ::: "memory")
#define CP_WAIT0()  asm volatile("cp.async.wait_group 0;" ::: "memory")
#define CP_WAIT1()  asm volatile("cp.async.wait_group 1;" ::: "memory")

// ============================================================
// fp16 tensor-core GEMM via wmma (single product).
// C[m,n] = sum_k A[m,k]*B[n,k]
// CTA tile 128x128, 8 warps 4(M)x2(N), warp tile 32x64, K-chunk 32,
// cp.async double-buffered smem, 2 CTAs/SM.
// EPI: 0 = bias, fp32 C + pack Q/K fp16 per head
//      1 = bias + exact GELU -> fp16 Ch
//      2 = bias + residual -> fp32 C
//      3 = scale + mask -> fp32 C (batched, scores)
// ============================================================
// smem per stage: A|B, each 128 rows x 48 half (stride 96B) = 12288B.
// GSMEM must also cover the 128x128 fp32 epilogue staging = 65536B.
#define SROW   48
#define MATB   12288
#define STAGEB 24576
#define GSMEM  65536

template<int EPI>
__global__ void __launch_bounds__(256, 2) tc_gemm(
    const __half* __restrict__ A, long aBatch,
    const __half* __restrict__ Bw, long bBatch,
    float* __restrict__ C, int ldc, long cBatch,
    __half* __restrict__ Ch,
    const float* __restrict__ bias, const float* __restrict__ resid,
    int K, const int* __restrict__ mask,
    __half* __restrict__ qh, __half* __restrict__ kh)
{
    extern __shared__ char smem[];
    __half* sbf = (__half*)smem;
    float* sf = (float*)smem;
    const uint32_t sb = smem_u32(smem);
    const int tid = threadIdx.x;
    const int wid = tid >> 5;
    const int wm = wid >> 1;       // 0..3
    const int wn = wid & 1;        // 0..1
    const int m0 = blockIdx.y * 128;
    const int n0 = blockIdx.x * 128;
    const int z  = blockIdx.z;

    A  += (size_t)z * aBatch;
    Bw += (size_t)z * bBatch;
    if (C) C += (size_t)z * cBatch;

    wmma::fragment<wmma::accumulator, 16, 16, 16, float> acc[2][4];
#pragma unroll
    for (int i = 0; i < 2; i++)
#pragma unroll
        for (int j = 0; j < 4; j++) wmma::fill_fragment(acc[i][j], 0.0f);

    const int nk = K >> 5;

    auto load_stage = [&](int st, int k0) {
        uint32_t base = sb + st * STAGEB;
#pragma unroll
        for (int v = tid; v < 1024; v += 256) {
            int mat = v >> 9;
            int rem = v & 511;
            int r = rem >> 2, cg = rem & 3;
            uint32_t so = mat * MATB + r * 96 + cg * 16;
            const __half* src = mat ? (Bw + (size_t)(n0 + r) * K + k0 + cg * 8)
                                    : (A  + (size_t)(m0 + r) * K + k0 + cg * 8);
            cp16(base + so, src);
        }
    };

    load_stage(0, 0);
    CP_COMMIT();

    for (int c = 0; c < nk; c++) {
        const int st = c & 1;
        if (c + 1 < nk) {
            load_stage(st ^ 1, (c + 1) << 5);
            CP_COMMIT();
            CP_WAIT1();
        } else {
            CP_WAIT0();
        }
        __syncthreads();

        const __half* As = sbf + st * (STAGEB/2);
        const __half* Bs = As + MATB/2;

#pragma unroll
        for (int kst = 0; kst < 2; kst++) {
            wmma::fragment<wmma::matrix_a, 16, 16, 16, __half, wmma::row_major> fa[2];
#pragma unroll
            for (int i = 0; i < 2; i++)
                wmma::load_matrix_sync(fa[i], As + (wm*32 + i*16) * SROW + kst * 16, SROW);
#pragma unroll
            for (int j = 0; j < 4; j++) {
                wmma::fragment<wmma::matrix_b, 16, 16, 16, __half, wmma::col_major> fb;
                wmma::load_matrix_sync(fb, Bs + (wn*64 + j*16) * SROW + kst * 16, SROW);
#pragma unroll
                for (int i = 0; i < 2; i++)
                    wmma::mma_sync(acc[i][j], fa[i], fb, acc[i][j]);
            }
        }
        __syncthreads();
    }

    // stage accumulators to smem (64KB region)
#pragma unroll
    for (int i = 0; i < 2; i++)
#pragma unroll
        for (int j = 0; j < 4; j++)
            wmma::store_matrix_sync(sf + (wm*32 + i*16) * 128 + wn*64 + j*16,
                                    acc[i][j], 128, wmma::mem_row_major);
    __syncthreads();

    // ---- epilogue: 64 elements per thread, coalesced over columns ----
#pragma unroll 4
    for (int it = 0; it < 64; it++) {
        const int idx = it * 256 + tid;
        const int r = idx >> 7;
        const int cc = idx & 127;
        const int row = m0 + r;
        const int col = n0 + cc;
        float v = sf[idx];
        if (EPI == 0) {
            v += bias[col];
            C[(size_t)row * ldc + col] = v;
            if (col < 2 * D_) {
                int b_ = row >> 10, s_ = row & 1023;
                int c2 = (col < D_) ? col : (col - D_);
                int zz = b_ * NH_ + c2 / HD_;
                size_t po = (size_t)zz * (S_*HD_) + (size_t)s_ * HD_ + (c2 % HD_);
                if (col < D_) qh[po] = __float2half(v);
                else          kh[po] = __float2half(v);
            }
        } else if (EPI == 1) {
            v += bias[col];
            v = 0.5f * v * (1.0f + erff(v * 0.70710678118654752f));
            Ch[(size_t)row * ldc + col] = __float2half(v);
        } else if (EPI == 2) {
            v += bias[col] + resid[(size_t)row * ldc + col];
            C[(size_t)row * ldc + col] = v;
        } else {
            v *= 0.07216878364870322f;  // 1/sqrt(192)
            const int b_ = z >> 2;
            if (mask[b_ * S_ + col] == 0) v = -1e30f;
            C[(size_t)row * ldc + col] = v;
        }
    }
}

// ============================================================
// fp32 -> fp16
__global__ void cvt_kernel(const float* __restrict__ in,
                           __half* __restrict__ o, size_t n)
{
    size_t i = ((size_t)blockIdx.x * blockDim.x + threadIdx.x) * 4;
    if (i >= n) return;
    float4 v = *(const float4*)(in + i);
    __half2 h0 = __floats2half2_rn(v.x, v.y);
    __half2 h1 = __floats2half2_rn(v.z, v.w);
    *(__half2*)(o + i)     = h0;
    *(__half2*)(o + i + 2) = h1;
}

// row max + exp-sum per score row
__global__ void rowstats_kernel()
{
    const int row = blockIdx.x;
    const int tid = threadIdx.x;
    const float* r = g_scores + (size_t)row * S_;
    float v0 = r[tid], v1 = r[tid+256], v2 = r[tid+512], v3 = r[tid+768];
    __shared__ float red[256];
    float mx = fmaxf(fmaxf(v0, v1), fmaxf(v2, v3));
    red[tid] = mx; __syncthreads();
    for (int st = 128; st > 0; st >>= 1) { if (tid < st) red[tid] = fmaxf(red[tid], red[tid+st]); __syncthreads(); }
    float m = red[0];
    __syncthreads();
    float se = __expf(v0 - m) + __expf(v1 - m) + __expf(v2 - m) + __expf(v3 - m);
    red[tid] = se; __syncthreads();
    for (int st = 128; st > 0; st >>= 1) { if (tid < st) red[tid] += red[tid+st]; __syncthreads(); }
    if (tid == 0) { g_m[row] = m; g_z[row] = red[0]; }
}

// w[z,k] = sum_q exp(s[q,k]-m_q)/z_q  — grid (64,4) x 256 threads
__global__ void colsum_kernel()
{
    const int zz = blockIdx.x;
    const int col = blockIdx.y * 256 + threadIdx.x;
    __shared__ float sm[S_], sz[S_];
    for (int q = threadIdx.x; q < S_; q += 256) { sm[q] = g_m[zz*S_+q]; sz[q] = 1.0f / g_z[zz*S_+q]; }
    __syncthreads();
    float acc = 0.f;
    const float* sc = g_scores + (size_t)zz * S_ * S_ + col;
    for (int q = 0; q < S_; q++) acc += __expf(sc[(size_t)q * S_] - sm[q]) * sz[q];
    g_w[zz*S_ + col] = acc;
}

__global__ void ctxmean_kernel()
{
    const int z = blockIdx.x;
    const int b = z >> 2, h = z & 3;
    const int d = threadIdx.x;
    __shared__ float w[S_];
    for (int k = d; k < S_; k += 192) w[k] = g_w[z*S_+k];
    __syncthreads();
    float acc = 0.f;
    const float* vb = g_qkv + (size_t)b * S_ * TD_ + 2*D_ + h*HD_ + d;
    for (int k = 0; k < S_; k++) acc += w[k] * vb[(size_t)k * TD_];
    g_ctxmean[b*D_ + h*HD_ + d] = acc * (1.0f / S_);
}

__global__ void idx_kernel(const int* __restrict__ mask)
{
    const int b = blockIdx.x, tid = threadIdx.x;
    __shared__ int red[256];
    int s = 0;
    for (int k = tid; k < S_; k += 256) s += mask[b*S_ + k];
    red[tid] = s; __syncthreads();
    for (int st = 128; st > 0; st >>= 1) { if (tid < st) red[tid] += red[tid+st]; __syncthreads(); }
    if (tid == 0) g_idx[b] = red[0] - 1;
}

__global__ void embed_kernel(
    const float* __restrict__ Wout, const float* __restrict__ bout,
    const float* __restrict__ Wasp, const float* __restrict__ basp,
    const float* __restrict__ Wopi, const float* __restrict__ bopi,
    const float* __restrict__ Wia,  const float* __restrict__ bia,
    const float* __restrict__ Wio,  const float* __restrict__ bio,
    float* __restrict__ out)
{
    const int b = blockIdx.x, tid = threadIdx.x;
    __shared__ float cm[D_], emb[D_], e1s[D_], e2s[D_];
    for (int d = tid; d < D_; d += 256) cm[d] = g_ctxmean[b*D_ + d];
    __syncthreads();
    for (int n = tid; n < D_; n += 256) {
        float a = bout[n];
        const float* wr = Wout + (size_t)n * D_;
        for (int d = 0; d < D_; d++) a += cm[d] * wr[d];
        emb[n] = a;
    }
    __syncthreads();
    for (int n = tid; n < D_; n += 256) {
        float a = basp[n], o = bopi[n];
        const float* wa = Wasp + (size_t)n * D_;
        const float* wo = Wopi + (size_t)n * D_;
        for (int d = 0; d < D_; d++) { a += emb[d] * wa[d]; o += emb[d] * wo[d]; }
        e1s[n] = a; e2s[n] = o;
    }
    __syncthreads();
    for (int d = tid; d < D_; d += 256) {
        g_e1[b*D_ + d] = e1s[d];
        g_e2[b*D_ + d] = e2s[d];
        out[O_E1 + (size_t)b*D_ + d] = e1s[d];
        out[O_E2 + (size_t)b*D_ + d] = e2s[d];
    }
    if (tid < 2) {
        float a = bia[tid];
        const float* w = Wia + (size_t)tid * D_;
        for (int d = 0; d < D_; d++) a += e1s[d] * w[d];
        out[O_IA + b*2 + tid] = a;
    } else if (tid < 4) {
        int c = tid - 2;
        float a = bio[c];
        const float* w = Wio + (size_t)c * D_;
        for (int d = 0; d < D_; d++) a += e2s[d] * w[d];
        out[O_IO + b*2 + c] = a;
    }
}

__global__ void build_se_kernel(const float* __restrict__ x)
{
    const int blk = blockIdx.x;
    const int b = blk >> 10, s = blk & 1023;
    const int idx = g_idx[b];
#pragma unroll
    for (int i = 0; i < 3; i++) {
        int d = threadIdx.x + i * 256;
        float xv = x[(size_t)blk * D_ + d];
        float e1v = g_e1[b*D_ + d], e2v = g_e2[b*D_ + d];
        float v1 = (s == idx) ? e2v : ((s == 0) ? e1v : xv);
        float v2 = (s == 0) ? e1v : ((s == idx) ? e2v : xv);
        g_h1[(size_t)blk * D_ + d] = v1;
        g_h2[(size_t)blk * D_ + d] = v2;
    }
}

// layernorm: fp32 out + fp16 out for next GEMM A
__global__ void ln_kernel(const float* __restrict__ in,
                          const float* __restrict__ g, const float* __restrict__ bt,
                          float* __restrict__ outp, __half* __restrict__ oh)
{
    const int row = blockIdx.x, tid = threadIdx.x;
    const float* r = in + (size_t)row * D_;
    float v0 = r[tid], v1 = r[tid+256], v2 = r[tid+512];
    __shared__ float red[256];
    red[tid] = v0 + v1 + v2; __syncthreads();
    for (int st = 128; st > 0; st >>= 1) { if (tid < st) red[tid] += red[tid+st]; __syncthreads(); }
    float mean = red[0] * (1.0f / D_);
    __syncthreads();
    float d0 = v0 - mean, d1 = v1 - mean, d2 = v2 - mean;
    red[tid] = d0*d0 + d1*d1 + d2*d2; __syncthreads();
    for (int st = 128; st > 0; st >>= 1) { if (tid < st) red[tid] += red[tid+st]; __syncthreads(); }
    float rstd = rsqrtf(red[0] * (1.0f / D_) + 1e-12f);
    float o0 = d0 * rstd * g[tid]     + bt[tid];
    float o1 = d1 * rstd * g[tid+256] + bt[tid+256];
    float o2 = d2 * rstd * g[tid+512] + bt[tid+512];
    float* o = outp + (size_t)row * D_;
    o[tid] = o0; o[tid+256] = o1; o[tid+512] = o2;
    size_t base = (size_t)row * D_;
    oh[base+tid]     = __float2half(o0);
    oh[base+tid+256] = __float2half(o1);
    oh[base+tid+512] = __float2half(o2);
}

__global__ void logits_kernel(const float* __restrict__ in, const float* __restrict__ W,
                              const float* __restrict__ bias, float* __restrict__ outp)
{
    const int row = blockIdx.x, tid = threadIdx.x;
    __shared__ float srow[D_];
    const float* r = in + (size_t)row * D_;
    srow[tid] = r[tid]; srow[tid+256] = r[tid+256]; srow[tid+512] = r[tid+512];
    __syncthreads();
    float a0 = 0.f, a1 = 0.f, a2 = 0.f;
    for (int d = tid; d < D_; d += 256) {
        float x = srow[d];
        a0 += x * W[d]; a1 += x * W[D_ + d]; a2 += x * W[2*D_ + d];
    }
    __shared__ float red[3][256];
    red[0][tid] = a0; red[1][tid] = a1; red[2][tid] = a2;
    __syncthreads();
    for (int st = 128; st > 0; st >>= 1) {
        if (tid < st) {
            red[0][tid] += red[0][tid+st];
            red[1][tid] += red[1][tid+st];
            red[2][tid] += red[2][tid+st];
        }
        __syncthreads();
    }
    if (tid < 3) outp[(size_t)row * C_ + tid] = red[tid][0] + bias[tid];
}

// ============================================================
extern "C" void kernel_launch(void* const* d_in, const int* in_sizes, int n_in,
                              void* d_out, int out_size)
{
    const float* x        = (const float*)d_in[0];
    const int*   mask     = (const int*)  d_in[1];
    const float* mha_in_w = (const float*)d_in[2];
    const float* mha_in_b = (const float*)d_in[3];
    const float* mha_out_w= (const float*)d_in[4];
    const float* mha_out_b= (const float*)d_in[5];
    const float* asp_w    = (const float*)d_in[6];
    const float* asp_b    = (const float*)d_in[7];
    const float* opi_w    = (const float*)d_in[8];
    const float* opi_b    = (const float*)d_in[9];
    const float* ia_w     = (const float*)d_in[10];
    const float* ia_b     = (const float*)d_in[11];
    const float* io_w     = (const float*)d_in[12];
    const float* io_b     = (const float*)d_in[13];
    const float* fwd_iw   = (const float*)d_in[14];
    const float* fwd_ib   = (const float*)d_in[15];
    const float* fwd_ow   = (const float*)d_in[16];
    const float* fwd_ob   = (const float*)d_in[17];
    const float* fwd_g    = (const float*)d_in[18];
    const float* fwd_bt   = (const float*)d_in[19];
    const float* rev_iw   = (const float*)d_in[20];
    const float* rev_ib   = (const float*)d_in[21];
    const float* rev_ow   = (const float*)d_in[22];
    const float* rev_ob   = (const float*)d_in[23];
    const float* rev_g    = (const float*)d_in[24];
    const float* rev_bt   = (const float*)d_in[25];
    const float* cls_a_w  = (const float*)d_in[26];
    const float* cls_a_b  = (const float*)d_in[27];
    const float* cls_o_w  = (const float*)d_in[28];
    const float* cls_o_b  = (const float*)d_in[29];
    float* out = (float*)d_out;

    float *qkvp, *h1, *h2, *tmp, *scoresp;
    __half *ah, *ih, *bh, *qh, *kh;
    cudaGetSymbolAddress((void**)&qkvp,    g_qkv);
    cudaGetSymbolAddress((void**)&scoresp, g_scores);
    cudaGetSymbolAddress((void**)&h1,   g_h1);
    cudaGetSymbolAddress((void**)&h2,   g_h2);
    cudaGetSymbolAddress((void**)&tmp,  g_tmp);
    cudaGetSymbolAddress((void**)&ah,   g_ah);
    cudaGetSymbolAddress((void**)&ih,   g_ih);
    cudaGetSymbolAddress((void**)&bh,   g_bh);
    cudaGetSymbolAddress((void**)&qh,   g_qh);
    cudaGetSymbolAddress((void**)&kh,   g_kh);

    cudaFuncSetAttribute(tc_gemm<0>, cudaFuncAttributeMaxDynamicSharedMemorySize, GSMEM);
    cudaFuncSetAttribute(tc_gemm<1>, cudaFuncAttributeMaxDynamicSharedMemorySize, GSMEM);
    cudaFuncSetAttribute(tc_gemm<2>, cudaFuncAttributeMaxDynamicSharedMemorySize, GSMEM);
    cudaFuncSetAttribute(tc_gemm<3>, cudaFuncAttributeMaxDynamicSharedMemorySize, GSMEM);

    auto cvt = [&](const float* src, __half* dst, size_t n) {
        cvt_kernel<<<(unsigned)((n/4 + 255) / 256), 256>>>(src, dst, n);
    };

    // 1) QKV projection; epilogue packs Q/K fp16 per head
    cvt(x, ah, (size_t)BS_ * D_);
    cvt(mha_in_w, bh, (size_t)TD_ * D_);
    tc_gemm<0><<<dim3(TD_/128, BS_/128, 1), 256, GSMEM>>>(
        ah, 0, bh, 0, qkvp, TD_, 0, nullptr,
        mha_in_b, nullptr, D_, nullptr, qh, kh);

    // 2) attention scores (batched over 64 z) + softmax stats + colsum + ctx mean
    tc_gemm<3><<<dim3(S_/128, S_/128, B_*NH_), 256, GSMEM>>>(
        qh, (long)S_*HD_, kh, (long)S_*HD_, scoresp, S_, (long)S_*S_, nullptr,
        nullptr, nullptr, HD_, mask, nullptr, nullptr);
    rowstats_kernel<<<B_*NH_*S_, 256>>>();
    colsum_kernel<<<dim3(B_*NH_, 4), 256>>>();
    ctxmean_kernel<<<B_*NH_, 192>>>();

    // 3) embedding path
    idx_kernel<<<B_, 256>>>(mask);
    embed_kernel<<<B_, 256>>>(mha_out_w, mha_out_b, asp_w, asp_b, opi_w, opi_b,
                              ia_w, ia_b, io_w, io_b, out);

    // 4) x passthrough
    cudaMemcpyAsync(out + O_X, x, sizeof(float) * (size_t)BS_ * D_, cudaMemcpyDeviceToDevice);

    // 5) build se1/se2
    build_se_kernel<<<BS_, 256>>>(x);

    // 6) decoder stacks on tensor cores
    struct Stack { float* h; const float *iw, *ib, *ow, *ob, *g, *bt; size_t oSE; }
    stacks[2] = {
        { h1, fwd_iw, fwd_ib, fwd_ow, fwd_ob, fwd_g, fwd_bt, O_SE1 },
        { h2, rev_iw, rev_ib, rev_ow, rev_ob, rev_g, rev_bt, O_SE2 },
    };
    for (int s = 0; s < 2; s++) {
        Stack& st = stacks[s];
        cvt(st.h, ah, (size_t)BS_ * D_);
        for (int l = 0; l < NL_; l++) {
            cvt(st.iw + (size_t)l*DFF_*D_, bh, (size_t)DFF_*D_);
            tc_gemm<1><<<dim3(DFF_/128, BS_/128, 1), 256, GSMEM>>>(
                ah, 0, bh, 0, nullptr, DFF_, 0, ih,
                st.ib + (size_t)l*DFF_, nullptr, D_, nullptr, nullptr, nullptr);
            cvt(st.ow + (size_t)l*D_*DFF_, bh, (size_t)D_*DFF_);
            tc_gemm<2><<<dim3(D_/128, BS_/128, 1), 256, GSMEM>>>(
                ih, 0, bh, 0, tmp, D_, 0, nullptr,
                st.ob + (size_t)l*D_, st.h, DFF_, nullptr, nullptr, nullptr);
            float* lnout = (l == NL_-1) ? (out + st.oSE) : st.h;
            ln_kernel<<<BS_, 256>>>(tmp, st.g + (size_t)l*D_, st.bt + (size_t)l*D_, lnout, ah);
        }
    }

    // 7) classifier logits
    logits_kernel<<<BS_, 256>>>(out + O_SE1, cls_a_w, cls_a_b, out + O_LA);
    logits_kernel<<<BS_, 256>>>(out + O_SE2, cls_o_w, cls_o_b, out + O_LO);
}

// round 8
// speedup vs baseline: 4.2760x; 1.0899x over previous
#include <cuda_runtime.h>
#include <cuda_fp16.h>
#include <mma.h>
#include <math.h>
#include <stdint.h>

using namespace nvcuda;

#define B_   16
#define S_   1024
#define D_   768
#define NH_  4
#define HD_  192
#define DFF_ 3072
#define NL_  2
#define C_   3
#define BS_  (B_*S_)     // 16384
#define TD_  (3*D_)      // 2304

// ---- output layout (floats) ----
#define O_LA  ((size_t)0)
#define O_LO  ((size_t)49152)
#define O_X   ((size_t)98304)
#define O_SE1 ((size_t)12681216)
#define O_SE2 ((size_t)25264128)
#define O_IA  ((size_t)37847040)
#define O_IO  ((size_t)37847072)
#define O_E1  ((size_t)37847104)
#define O_E2  ((size_t)37859392)

// ---- scratch (device globals) ----
__device__ float g_qkv[(size_t)BS_*TD_];
__device__ float g_scores[(size_t)B_*NH_*S_*S_];
__device__ float g_m[B_*NH_*S_];
__device__ float g_z[B_*NH_*S_];
__device__ float g_w[B_*NH_*S_];
__device__ float g_ctxmean[B_*D_];
__device__ float g_e1[B_*D_];
__device__ float g_e2[B_*D_];
__device__ int   g_idx[B_];
__device__ float g_h1[(size_t)BS_*D_];
__device__ float g_h2[(size_t)BS_*D_];
__device__ float g_tmp[(size_t)BS_*D_];

// fp16 operand buffers
__device__ __half g_ah[(size_t)BS_*D_];
__device__ __half g_ih[(size_t)BS_*DFF_];
__device__ __half g_bh[(size_t)DFF_*D_];
__device__ __half g_qh[(size_t)B_*NH_*S_*HD_];
__device__ __half g_kh[(size_t)B_*NH_*S_*HD_];

// ============================================================
__device__ __forceinline__ uint32_t smem_u32(const void* p) {
    uint32_t a;
    asm("{ .reg .u64 t; cvta.to.shared.u64 t, %1; cvt.u32.u64 %0, t; }" : "=r"(a) : "l"(p));
    return a;
}
__device__ __forceinline__ void cp16(uint32_t dst, const void* src) {
    asm volatile("cp.async.cg.shared.global [%0], [%1], 16;" :: "r"(dst), "l"(src));
}
#define CP_COMMIT() asm volatile("cp.async.commit_group;" ::: "memory")
#define CP_WAIT0()  asm volatile("cp.async.wait_group 0;" ::: "memory")
#define CP_WAIT1()  asm volatile("cp.async.wait_group 1;" ::: "memory")

// ============================================================
// fp16 tensor-core GEMM via wmma (single product).
// C[m,n] = sum_k A[m,k]*B[n,k]
// CTA tile 128x128, 4 warps in 2(M)x2(N), warp tile 64x64, K-chunk 32,
// cp.async double-buffered smem, 2 CTAs/SM (128 thr, <=256 regs).
// Larger warp tile: A/B smem read duplication 2x/2x (was 2x/4x).
// EPI: 0 = bias, fp32 C + pack Q/K fp16 per head
//      1 = bias + exact GELU -> fp16 Ch
//      2 = bias + residual -> fp32 C
//      3 = scale + mask -> fp32 C (batched, scores)
// ============================================================
// smem per stage: A|B, each 128 rows x 48 half (stride 96B) = 12288B.
// GSMEM covers the 128x128 fp32 epilogue staging = 65536B.
#define SROW   48
#define MATB   12288
#define STAGEB 24576
#define GSMEM  65536

template<int EPI>
__global__ void __launch_bounds__(128, 2) tc_gemm(
    const __half* __restrict__ A, long aBatch,
    const __half* __restrict__ Bw, long bBatch,
    float* __restrict__ C, int ldc, long cBatch,
    __half* __restrict__ Ch,
    const float* __restrict__ bias, const float* __restrict__ resid,
    int K, const int* __restrict__ mask,
    __half* __restrict__ qh, __half* __restrict__ kh)
{
    extern __shared__ char smem[];
    __half* sbf = (__half*)smem;
    float* sf = (float*)smem;
    const uint32_t sb = smem_u32(smem);
    const int tid = threadIdx.x;
    const int wid = tid >> 5;
    const int wm = wid >> 1;       // 0..1
    const int wn = wid & 1;        // 0..1
    const int m0 = blockIdx.y * 128;
    const int n0 = blockIdx.x * 128;
    const int z  = blockIdx.z;

    A  += (size_t)z * aBatch;
    Bw += (size_t)z * bBatch;
    if (C) C += (size_t)z * cBatch;

    wmma::fragment<wmma::accumulator, 16, 16, 16, float> acc[4][4];
#pragma unroll
    for (int i = 0; i < 4; i++)
#pragma unroll
        for (int j = 0; j < 4; j++) wmma::fill_fragment(acc[i][j], 0.0f);

    const int nk = K >> 5;

    auto load_stage = [&](int st, int k0) {
        uint32_t base = sb + st * STAGEB;
#pragma unroll
        for (int v = tid; v < 1024; v += 128) {
            int mat = v >> 9;
            int rem = v & 511;
            int r = rem >> 2, cg = rem & 3;
            uint32_t so = mat * MATB + r * 96 + cg * 16;
            const __half* src = mat ? (Bw + (size_t)(n0 + r) * K + k0 + cg * 8)
                                    : (A  + (size_t)(m0 + r) * K + k0 + cg * 8);
            cp16(base + so, src);
        }
    };

    load_stage(0, 0);
    CP_COMMIT();

    for (int c = 0; c < nk; c++) {
        const int st = c & 1;
        if (c + 1 < nk) {
            load_stage(st ^ 1, (c + 1) << 5);
            CP_COMMIT();
            CP_WAIT1();
        } else {
            CP_WAIT0();
        }
        __syncthreads();

        const __half* As = sbf + st * (STAGEB/2);
        const __half* Bs = As + MATB/2;

#pragma unroll
        for (int kst = 0; kst < 2; kst++) {
            wmma::fragment<wmma::matrix_a, 16, 16, 16, __half, wmma::row_major> fa[4];
#pragma unroll
            for (int i = 0; i < 4; i++)
                wmma::load_matrix_sync(fa[i], As + (wm*64 + i*16) * SROW + kst * 16, SROW);
#pragma unroll
            for (int j = 0; j < 4; j++) {
                wmma::fragment<wmma::matrix_b, 16, 16, 16, __half, wmma::col_major> fb;
                wmma::load_matrix_sync(fb, Bs + (wn*64 + j*16) * SROW + kst * 16, SROW);
#pragma unroll
                for (int i = 0; i < 4; i++)
                    wmma::mma_sync(acc[i][j], fa[i], fb, acc[i][j]);
            }
        }
        __syncthreads();
    }

    // stage accumulators to smem (64KB region)
#pragma unroll
    for (int i = 0; i < 4; i++)
#pragma unroll
        for (int j = 0; j < 4; j++)
            wmma::store_matrix_sync(sf + (wm*64 + i*16) * 128 + wn*64 + j*16,
                                    acc[i][j], 128, wmma::mem_row_major);
    __syncthreads();

    // ---- epilogue: 128 elements per thread, coalesced over columns ----
#pragma unroll 4
    for (int it = 0; it < 128; it++) {
        const int idx = it * 128 + tid;
        const int r = idx >> 7;
        const int cc = idx & 127;
        const int row = m0 + r;
        const int col = n0 + cc;
        float v = sf[idx];
        if (EPI == 0) {
            v += bias[col];
            C[(size_t)row * ldc + col] = v;
            if (col < 2 * D_) {
                int b_ = row >> 10, s_ = row & 1023;
                int c2 = (col < D_) ? col : (col - D_);
                int zz = b_ * NH_ + c2 / HD_;
                size_t po = (size_t)zz * (S_*HD_) + (size_t)s_ * HD_ + (c2 % HD_);
                if (col < D_) qh[po] = __float2half(v);
                else          kh[po] = __float2half(v);
            }
        } else if (EPI == 1) {
            v += bias[col];
            v = 0.5f * v * (1.0f + erff(v * 0.70710678118654752f));
            Ch[(size_t)row * ldc + col] = __float2half(v);
        } else if (EPI == 2) {
            v += bias[col] + resid[(size_t)row * ldc + col];
            C[(size_t)row * ldc + col] = v;
        } else {
            v *= 0.07216878364870322f;  // 1/sqrt(192)
            const int b_ = z >> 2;
            if (mask[b_ * S_ + col] == 0) v = -1e30f;
            C[(size_t)row * ldc + col] = v;
        }
    }
}

// ============================================================
// fp32 -> fp16
__global__ void cvt_kernel(const float* __restrict__ in,
                           __half* __restrict__ o, size_t n)
{
    size_t i = ((size_t)blockIdx.x * blockDim.x + threadIdx.x) * 4;
    if (i >= n) return;
    float4 v = *(const float4*)(in + i);
    __half2 h0 = __floats2half2_rn(v.x, v.y);
    __half2 h1 = __floats2half2_rn(v.z, v.w);
    *(__half2*)(o + i)     = h0;
    *(__half2*)(o + i + 2) = h1;
}

// row max + exp-sum per score row
__global__ void rowstats_kernel()
{
    const int row = blockIdx.x;
    const int tid = threadIdx.x;
    const float* r = g_scores + (size_t)row * S_;
    float v0 = r[tid], v1 = r[tid+256], v2 = r[tid+512], v3 = r[tid+768];
    __shared__ float red[256];
    float mx = fmaxf(fmaxf(v0, v1), fmaxf(v2, v3));
    red[tid] = mx; __syncthreads();
    for (int st = 128; st > 0; st >>= 1) { if (tid < st) red[tid] = fmaxf(red[tid], red[tid+st]); __syncthreads(); }
    float m = red[0];
    __syncthreads();
    float se = __expf(v0 - m) + __expf(v1 - m) + __expf(v2 - m) + __expf(v3 - m);
    red[tid] = se; __syncthreads();
    for (int st = 128; st > 0; st >>= 1) { if (tid < st) red[tid] += red[tid+st]; __syncthreads(); }
    if (tid == 0) { g_m[row] = m; g_z[row] = red[0]; }
}

// w[z,k] = sum_q exp(s[q,k]-m_q)/z_q  — grid (64,4) x 256 threads
__global__ void colsum_kernel()
{
    const int zz = blockIdx.x;
    const int col = blockIdx.y * 256 + threadIdx.x;
    __shared__ float sm[S_], sz[S_];
    for (int q = threadIdx.x; q < S_; q += 256) { sm[q] = g_m[zz*S_+q]; sz[q] = 1.0f / g_z[zz*S_+q]; }
    __syncthreads();
    float acc = 0.f;
    const float* sc = g_scores + (size_t)zz * S_ * S_ + col;
    for (int q = 0; q < S_; q++) acc += __expf(sc[(size_t)q * S_] - sm[q]) * sz[q];
    g_w[zz*S_ + col] = acc;
}

__global__ void ctxmean_kernel()
{
    const int z = blockIdx.x;
    const int b = z >> 2, h = z & 3;
    const int d = threadIdx.x;
    __shared__ float w[S_];
    for (int k = d; k < S_; k += 192) w[k] = g_w[z*S_+k];
    __syncthreads();
    float acc = 0.f;
    const float* vb = g_qkv + (size_t)b * S_ * TD_ + 2*D_ + h*HD_ + d;
    for (int k = 0; k < S_; k++) acc += w[k] * vb[(size_t)k * TD_];
    g_ctxmean[b*D_ + h*HD_ + d] = acc * (1.0f / S_);
}

__global__ void idx_kernel(const int* __restrict__ mask)
{
    const int b = blockIdx.x, tid = threadIdx.x;
    __shared__ int red[256];
    int s = 0;
    for (int k = tid; k < S_; k += 256) s += mask[b*S_ + k];
    red[tid] = s; __syncthreads();
    for (int st = 128; st > 0; st >>= 1) { if (tid < st) red[tid] += red[tid+st]; __syncthreads(); }
    if (tid == 0) g_idx[b] = red[0] - 1;
}

__global__ void embed_kernel(
    const float* __restrict__ Wout, const float* __restrict__ bout,
    const float* __restrict__ Wasp, const float* __restrict__ basp,
    const float* __restrict__ Wopi, const float* __restrict__ bopi,
    const float* __restrict__ Wia,  const float* __restrict__ bia,
    const float* __restrict__ Wio,  const float* __restrict__ bio,
    float* __restrict__ out)
{
    const int b = blockIdx.x, tid = threadIdx.x;
    __shared__ float cm[D_], emb[D_], e1s[D_], e2s[D_];
    for (int d = tid; d < D_; d += 256) cm[d] = g_ctxmean[b*D_ + d];
    __syncthreads();
    for (int n = tid; n < D_; n += 256) {
        float a = bout[n];
        const float* wr = Wout + (size_t)n * D_;
        for (int d = 0; d < D_; d++) a += cm[d] * wr[d];
        emb[n] = a;
    }
    __syncthreads();
    for (int n = tid; n < D_; n += 256) {
        float a = basp[n], o = bopi[n];
        const float* wa = Wasp + (size_t)n * D_;
        const float* wo = Wopi + (size_t)n * D_;
        for (int d = 0; d < D_; d++) { a += emb[d] * wa[d]; o += emb[d] * wo[d]; }
        e1s[n] = a; e2s[n] = o;
    }
    __syncthreads();
    for (int d = tid; d < D_; d += 256) {
        g_e1[b*D_ + d] = e1s[d];
        g_e2[b*D_ + d] = e2s[d];
        out[O_E1 + (size_t)b*D_ + d] = e1s[d];
        out[O_E2 + (size_t)b*D_ + d] = e2s[d];
    }
    if (tid < 2) {
        float a = bia[tid];
        const float* w = Wia + (size_t)tid * D_;
        for (int d = 0; d < D_; d++) a += e1s[d] * w[d];
        out[O_IA + b*2 + tid] = a;
    } else if (tid < 4) {
        int c = tid - 2;
        float a = bio[c];
        const float* w = Wio + (size_t)c * D_;
        for (int d = 0; d < D_; d++) a += e2s[d] * w[d];
        out[O_IO + b*2 + c] = a;
    }
}

__global__ void build_se_kernel(const float* __restrict__ x)
{
    const int blk = blockIdx.x;
    const int b = blk >> 10, s = blk & 1023;
    const int idx = g_idx[b];
#pragma unroll
    for (int i = 0; i < 3; i++) {
        int d = threadIdx.x + i * 256;
        float xv = x[(size_t)blk * D_ + d];
        float e1v = g_e1[b*D_ + d], e2v = g_e2[b*D_ + d];
        float v1 = (s == idx) ? e2v : ((s == 0) ? e1v : xv);
        float v2 = (s == 0) ? e1v : ((s == idx) ? e2v : xv);
        g_h1[(size_t)blk * D_ + d] = v1;
        g_h2[(size_t)blk * D_ + d] = v2;
    }
}

// layernorm: fp32 out + fp16 out for next GEMM A
__global__ void ln_kernel(const float* __restrict__ in,
                          const float* __restrict__ g, const float* __restrict__ bt,
                          float* __restrict__ outp, __half* __restrict__ oh)
{
    const int row = blockIdx.x, tid = threadIdx.x;
    const float* r = in + (size_t)row * D_;
    float v0 = r[tid], v1 = r[tid+256], v2 = r[tid+512];
    __shared__ float red[256];
    red[tid] = v0 + v1 + v2; __syncthreads();
    for (int st = 128; st > 0; st >>= 1) { if (tid < st) red[tid] += red[tid+st]; __syncthreads(); }
    float mean = red[0] * (1.0f / D_);
    __syncthreads();
    float d0 = v0 - mean, d1 = v1 - mean, d2 = v2 - mean;
    red[tid] = d0*d0 + d1*d1 + d2*d2; __syncthreads();
    for (int st = 128; st > 0; st >>= 1) { if (tid < st) red[tid] += red[tid+st]; __syncthreads(); }
    float rstd = rsqrtf(red[0] * (1.0f / D_) + 1e-12f);
    float o0 = d0 * rstd * g[tid]     + bt[tid];
    float o1 = d1 * rstd * g[tid+256] + bt[tid+256];
    float o2 = d2 * rstd * g[tid+512] + bt[tid+512];
    float* o = outp + (size_t)row * D_;
    o[tid] = o0; o[tid+256] = o1; o[tid+512] = o2;
    size_t base = (size_t)row * D_;
    oh[base+tid]     = __float2half(o0);
    oh[base+tid+256] = __float2half(o1);
    oh[base+tid+512] = __float2half(o2);
}

__global__ void logits_kernel(const float* __restrict__ in, const float* __restrict__ W,
                              const float* __restrict__ bias, float* __restrict__ outp)
{
    const int row = blockIdx.x, tid = threadIdx.x;
    __shared__ float srow[D_];
    const float* r = in + (size_t)row * D_;
    srow[tid] = r[tid]; srow[tid+256] = r[tid+256]; srow[tid+512] = r[tid+512];
    __syncthreads();
    float a0 = 0.f, a1 = 0.f, a2 = 0.f;
    for (int d = tid; d < D_; d += 256) {
        float x = srow[d];
        a0 += x * W[d]; a1 += x * W[D_ + d]; a2 += x * W[2*D_ + d];
    }
    __shared__ float red[3][256];
    red[0][tid] = a0; red[1][tid] = a1; red[2][tid] = a2;
    __syncthreads();
    for (int st = 128; st > 0; st >>= 1) {
        if (tid < st) {
            red[0][tid] += red[0][tid+st];
            red[1][tid] += red[1][tid+st];
            red[2][tid] += red[2][tid+st];
        }
        __syncthreads();
    }
    if (tid < 3) outp[(size_t)row * C_ + tid] = red[tid][0] + bias[tid];
}

// ============================================================
extern "C" void kernel_launch(void* const* d_in, const int* in_sizes, int n_in,
                              void* d_out, int out_size)
{
    const float* x        = (const float*)d_in[0];
    const int*   mask     = (const int*)  d_in[1];
    const float* mha_in_w = (const float*)d_in[2];
    const float* mha_in_b = (const float*)d_in[3];
    const float* mha_out_w= (const float*)d_in[4];
    const float* mha_out_b= (const float*)d_in[5];
    const float* asp_w    = (const float*)d_in[6];
    const float* asp_b    = (const float*)d_in[7];
    const float* opi_w    = (const float*)d_in[8];
    const float* opi_b    = (const float*)d_in[9];
    const float* ia_w     = (const float*)d_in[10];
    const float* ia_b     = (const float*)d_in[11];
    const float* io_w     = (const float*)d_in[12];
    const float* io_b     = (const float*)d_in[13];
    const float* fwd_iw   = (const float*)d_in[14];
    const float* fwd_ib   = (const float*)d_in[15];
    const float* fwd_ow   = (const float*)d_in[16];
    const float* fwd_ob   = (const float*)d_in[17];
    const float* fwd_g    = (const float*)d_in[18];
    const float* fwd_bt   = (const float*)d_in[19];
    const float* rev_iw   = (const float*)d_in[20];
    const float* rev_ib   = (const float*)d_in[21];
    const float* rev_ow   = (const float*)d_in[22];
    const float* rev_ob   = (const float*)d_in[23];
    const float* rev_g    = (const float*)d_in[24];
    const float* rev_bt   = (const float*)d_in[25];
    const float* cls_a_w  = (const float*)d_in[26];
    const float* cls_a_b  = (const float*)d_in[27];
    const float* cls_o_w  = (const float*)d_in[28];
    const float* cls_o_b  = (const float*)d_in[29];
    float* out = (float*)d_out;

    float *qkvp, *h1, *h2, *tmp, *scoresp;
    __half *ah, *ih, *bh, *qh, *kh;
    cudaGetSymbolAddress((void**)&qkvp,    g_qkv);
    cudaGetSymbolAddress((void**)&scoresp, g_scores);
    cudaGetSymbolAddress((void**)&h1,   g_h1);
    cudaGetSymbolAddress((void**)&h2,   g_h2);
    cudaGetSymbolAddress((void**)&tmp,  g_tmp);
    cudaGetSymbolAddress((void**)&ah,   g_ah);
    cudaGetSymbolAddress((void**)&ih,   g_ih);
    cudaGetSymbolAddress((void**)&bh,   g_bh);
    cudaGetSymbolAddress((void**)&qh,   g_qh);
    cudaGetSymbolAddress((void**)&kh,   g_kh);

    cudaFuncSetAttribute(tc_gemm<0>, cudaFuncAttributeMaxDynamicSharedMemorySize, GSMEM);
    cudaFuncSetAttribute(tc_gemm<1>, cudaFuncAttributeMaxDynamicSharedMemorySize, GSMEM);
    cudaFuncSetAttribute(tc_gemm<2>, cudaFuncAttributeMaxDynamicSharedMemorySize, GSMEM);
    cudaFuncSetAttribute(tc_gemm<3>, cudaFuncAttributeMaxDynamicSharedMemorySize, GSMEM);

    auto cvt = [&](const float* src, __half* dst, size_t n) {
        cvt_kernel<<<(unsigned)((n/4 + 255) / 256), 256>>>(src, dst, n);
    };

    // 1) QKV projection; epilogue packs Q/K fp16 per head
    cvt(x, ah, (size_t)BS_ * D_);
    cvt(mha_in_w, bh, (size_t)TD_ * D_);
    tc_gemm<0><<<dim3(TD_/128, BS_/128, 1), 128, GSMEM>>>(
        ah, 0, bh, 0, qkvp, TD_, 0, nullptr,
        mha_in_b, nullptr, D_, nullptr, qh, kh);

    // 2) attention scores (batched over 64 z) + softmax stats + colsum + ctx mean
    tc_gemm<3><<<dim3(S_/128, S_/128, B_*NH_), 128, GSMEM>>>(
        qh, (long)S_*HD_, kh, (long)S_*HD_, scoresp, S_, (long)S_*S_, nullptr,
        nullptr, nullptr, HD_, mask, nullptr, nullptr);
    rowstats_kernel<<<B_*NH_*S_, 256>>>();
    colsum_kernel<<<dim3(B_*NH_, 4), 256>>>();
    ctxmean_kernel<<<B_*NH_, 192>>>();

    // 3) embedding path
    idx_kernel<<<B_, 256>>>(mask);
    embed_kernel<<<B_, 256>>>(mha_out_w, mha_out_b, asp_w, asp_b, opi_w, opi_b,
                              ia_w, ia_b, io_w, io_b, out);

    // 4) x passthrough
    cudaMemcpyAsync(out + O_X, x, sizeof(float) * (size_t)BS_ * D_, cudaMemcpyDeviceToDevice);

    // 5) build se1/se2
    build_se_kernel<<<BS_, 256>>>(x);

    // 6) decoder stacks on tensor cores
    struct Stack { float* h; const float *iw, *ib, *ow, *ob, *g, *bt; size_t oSE; }
    stacks[2] = {
        { h1, fwd_iw, fwd_ib, fwd_ow, fwd_ob, fwd_g, fwd_bt, O_SE1 },
        { h2, rev_iw, rev_ib, rev_ow, rev_ob, rev_g, rev_bt, O_SE2 },
    };
    for (int s = 0; s < 2; s++) {
        Stack& st = stacks[s];
        cvt(st.h, ah, (size_t)BS_ * D_);
        for (int l = 0; l < NL_; l++) {
            cvt(st.iw + (size_t)l*DFF_*D_, bh, (size_t)DFF_*D_);
            tc_gemm<1><<<dim3(DFF_/128, BS_/128, 1), 128, GSMEM>>>(
                ah, 0, bh, 0, nullptr, DFF_, 0, ih,
                st.ib + (size_t)l*DFF_, nullptr, D_, nullptr, nullptr, nullptr);
            cvt(st.ow + (size_t)l*D_*DFF_, bh, (size_t)D_*DFF_);
            tc_gemm<2><<<dim3(D_/128, BS_/128, 1), 128, GSMEM>>>(
                ih, 0, bh, 0, tmp, D_, 0, nullptr,
                st.ob + (size_t)l*D_, st.h, DFF_, nullptr, nullptr, nullptr);
            float* lnout = (l == NL_-1) ? (out + st.oSE) : st.h;
            ln_kernel<<<BS_, 256>>>(tmp, st.g + (size_t)l*D_, st.bt + (size_t)l*D_, lnout, ah);
        }
    }

    // 7) classifier logits
    logits_kernel<<<BS_, 256>>>(out + O_SE1, cls_a_w, cls_a_b, out + O_LA);
    logits_kernel<<<BS_, 256>>>(out + O_SE2, cls_o_w, cls_o_b, out + O_LO);
}

// round 9
// speedup vs baseline: 4.4389x; 1.0381x over previous
#include <cuda_runtime.h>
#include <cuda_fp16.h>
#include <mma.h>
#include <math.h>
#include <stdint.h>

using namespace nvcuda;

#define B_   16
#define S_   1024
#define D_   768
#define NH_  4
#define HD_  192
#define DFF_ 3072
#define NL_  2
#define C_   3
#define BS_  (B_*S_)     // 16384
#define TD_  (3*D_)      // 2304

// ---- output layout (floats) ----
#define O_LA  ((size_t)0)
#define O_LO  ((size_t)49152)
#define O_X   ((size_t)98304)
#define O_SE1 ((size_t)12681216)
#define O_SE2 ((size_t)25264128)
#define O_IA  ((size_t)37847040)
#define O_IO  ((size_t)37847072)
#define O_E1  ((size_t)37847104)
#define O_E2  ((size_t)37859392)

// ---- scratch (device globals) ----
__device__ float g_qkv[(size_t)BS_*TD_];
__device__ float g_scores[(size_t)B_*NH_*S_*S_];
__device__ float g_m[B_*NH_*S_];
__device__ float g_z[B_*NH_*S_];
__device__ float g_w[B_*NH_*S_];
__device__ float g_ctxmean[B_*D_];
__device__ float g_e1[B_*D_];
__device__ float g_e2[B_*D_];
__device__ int   g_idx[B_];
__device__ float g_h1[(size_t)BS_*D_];
__device__ float g_h2[(size_t)BS_*D_];
__device__ float g_tmp[(size_t)BS_*D_];

// fp16 operand buffers
__device__ __half g_ah[(size_t)BS_*D_];
__device__ __half g_ih[(size_t)BS_*DFF_];
__device__ __half g_bh[(size_t)DFF_*D_];
__device__ __half g_qh[(size_t)B_*NH_*S_*HD_];
__device__ __half g_kh[(size_t)B_*NH_*S_*HD_];

// ============================================================
__device__ __forceinline__ uint32_t smem_u32(const void* p) {
    uint32_t a;
    asm("{ .reg .u64 t; cvta.to.shared.u64 t, %1; cvt.u32.u64 %0, t; }" : "=r"(a) : "l"(p));
    return a;
}
__device__ __forceinline__ void cp16(uint32_t dst, const void* src) {
    asm volatile("cp.async.cg.shared.global [%0], [%1], 16;" :: "r"(dst), "l"(src));
}
#define CP_COMMIT() asm volatile("cp.async.commit_group;" ::: "memory")
#define CP_WAIT0()  asm volatile("cp.async.wait_group 0;" ::: "memory")
#define CP_WAIT1()  asm volatile("cp.async.wait_group 1;" ::: "memory")

// ============================================================
// fp16 tensor-core GEMM via wmma (single product).
// C[m,n] = sum_k A[m,k]*B[n,k]
// CTA tile 128x128, 4 warps in 2(M)x2(N), warp tile 64x64, K-chunk 64,
// cp.async double-buffered smem, 2 CTAs/SM.
// SROW=72 halves (144B stride): row i at 16*i mod 128 -> all 8 smem
// phases covered -> conflict-free LDSM fragment loads.
// EPI: 0 = bias, fp32 C + pack Q/K fp16 per head
//      1 = bias + exact GELU -> fp16 Ch
//      2 = bias + residual -> fp32 C
//      3 = scale + mask -> fp32 C (batched, scores)
// ============================================================
// smem per stage: A|B, each 128 rows x 72 half (144B) = 18432B.
#define SROW   72
#define MATB   18432
#define STAGEB 36864
#define GSMEM  73728   // 2 stages; also covers 64KB fp32 epilogue staging

template<int EPI>
__global__ void __launch_bounds__(128, 2) tc_gemm(
    const __half* __restrict__ A, long aBatch,
    const __half* __restrict__ Bw, long bBatch,
    float* __restrict__ C, int ldc, long cBatch,
    __half* __restrict__ Ch,
    const float* __restrict__ bias, const float* __restrict__ resid,
    int K, const int* __restrict__ mask,
    __half* __restrict__ qh, __half* __restrict__ kh)
{
    extern __shared__ char smem[];
    __half* sbf = (__half*)smem;
    float* sf = (float*)smem;
    const uint32_t sb = smem_u32(smem);
    const int tid = threadIdx.x;
    const int wid = tid >> 5;
    const int wm = wid >> 1;       // 0..1
    const int wn = wid & 1;        // 0..1
    const int m0 = blockIdx.y * 128;
    const int n0 = blockIdx.x * 128;
    const int z  = blockIdx.z;

    A  += (size_t)z * aBatch;
    Bw += (size_t)z * bBatch;
    if (C) C += (size_t)z * cBatch;

    wmma::fragment<wmma::accumulator, 16, 16, 16, float> acc[4][4];
#pragma unroll
    for (int i = 0; i < 4; i++)
#pragma unroll
        for (int j = 0; j < 4; j++) wmma::fill_fragment(acc[i][j], 0.0f);

    const int nk = K >> 6;

    // stage: 128 rows x 64 halves per matrix = 1024 16B-chunks per matrix
    auto load_stage = [&](int st, int k0) {
        uint32_t base = sb + st * STAGEB;
#pragma unroll
        for (int v = tid; v < 2048; v += 128) {
            int mat = v >> 10;
            int rem = v & 1023;
            int r = rem >> 3, cg = rem & 7;
            uint32_t so = mat * MATB + r * 144 + cg * 16;
            const __half* src = mat ? (Bw + (size_t)(n0 + r) * K + k0 + cg * 8)
                                    : (A  + (size_t)(m0 + r) * K + k0 + cg * 8);
            cp16(base + so, src);
        }
    };

    load_stage(0, 0);
    CP_COMMIT();

    for (int c = 0; c < nk; c++) {
        const int st = c & 1;
        if (c + 1 < nk) {
            load_stage(st ^ 1, (c + 1) << 6);
            CP_COMMIT();
            CP_WAIT1();
        } else {
            CP_WAIT0();
        }
        __syncthreads();

        const __half* As = sbf + st * (STAGEB/2);
        const __half* Bs = As + MATB/2;

#pragma unroll
        for (int kst = 0; kst < 4; kst++) {
            wmma::fragment<wmma::matrix_a, 16, 16, 16, __half, wmma::row_major> fa[4];
#pragma unroll
            for (int i = 0; i < 4; i++)
                wmma::load_matrix_sync(fa[i], As + (wm*64 + i*16) * SROW + kst * 16, SROW);
#pragma unroll
            for (int j = 0; j < 4; j++) {
                wmma::fragment<wmma::matrix_b, 16, 16, 16, __half, wmma::col_major> fb;
                wmma::load_matrix_sync(fb, Bs + (wn*64 + j*16) * SROW + kst * 16, SROW);
#pragma unroll
                for (int i = 0; i < 4; i++)
                    wmma::mma_sync(acc[i][j], fa[i], fb, acc[i][j]);
            }
        }
        __syncthreads();
    }

    // stage accumulators to smem
#pragma unroll
    for (int i = 0; i < 4; i++)
#pragma unroll
        for (int j = 0; j < 4; j++)
            wmma::store_matrix_sync(sf + (wm*64 + i*16) * 128 + wn*64 + j*16,
                                    acc[i][j], 128, wmma::mem_row_major);
    __syncthreads();

    // ---- epilogue: 128 elements per thread, coalesced over columns ----
#pragma unroll 4
    for (int it = 0; it < 128; it++) {
        const int idx = it * 128 + tid;
        const int r = idx >> 7;
        const int cc = idx & 127;
        const int row = m0 + r;
        const int col = n0 + cc;
        float v = sf[idx];
        if (EPI == 0) {
            v += bias[col];
            C[(size_t)row * ldc + col] = v;
            if (col < 2 * D_) {
                int b_ = row >> 10, s_ = row & 1023;
                int c2 = (col < D_) ? col : (col - D_);
                int zz = b_ * NH_ + c2 / HD_;
                size_t po = (size_t)zz * (S_*HD_) + (size_t)s_ * HD_ + (c2 % HD_);
                if (col < D_) qh[po] = __float2half(v);
                else          kh[po] = __float2half(v);
            }
        } else if (EPI == 1) {
            v += bias[col];
            v = 0.5f * v * (1.0f + erff(v * 0.70710678118654752f));
            Ch[(size_t)row * ldc + col] = __float2half(v);
        } else if (EPI == 2) {
            v += bias[col] + resid[(size_t)row * ldc + col];
            C[(size_t)row * ldc + col] = v;
        } else {
            v *= 0.07216878364870322f;  // 1/sqrt(192)
            const int b_ = z >> 2;
            if (mask[b_ * S_ + col] == 0) v = -1e30f;
            C[(size_t)row * ldc + col] = v;
        }
    }
}

// ============================================================
// fp32 -> fp16
__global__ void cvt_kernel(const float* __restrict__ in,
                           __half* __restrict__ o, size_t n)
{
    size_t i = ((size_t)blockIdx.x * blockDim.x + threadIdx.x) * 4;
    if (i >= n) return;
    float4 v = *(const float4*)(in + i);
    __half2 h0 = __floats2half2_rn(v.x, v.y);
    __half2 h1 = __floats2half2_rn(v.z, v.w);
    *(__half2*)(o + i)     = h0;
    *(__half2*)(o + i + 2) = h1;
}

// row max + exp-sum per score row
__global__ void rowstats_kernel()
{
    const int row = blockIdx.x;
    const int tid = threadIdx.x;
    const float* r = g_scores + (size_t)row * S_;
    float v0 = r[tid], v1 = r[tid+256], v2 = r[tid+512], v3 = r[tid+768];
    __shared__ float red[256];
    float mx = fmaxf(fmaxf(v0, v1), fmaxf(v2, v3));
    red[tid] = mx; __syncthreads();
    for (int st = 128; st > 0; st >>= 1) { if (tid < st) red[tid] = fmaxf(red[tid], red[tid+st]); __syncthreads(); }
    float m = red[0];
    __syncthreads();
    float se = __expf(v0 - m) + __expf(v1 - m) + __expf(v2 - m) + __expf(v3 - m);
    red[tid] = se; __syncthreads();
    for (int st = 128; st > 0; st >>= 1) { if (tid < st) red[tid] += red[tid+st]; __syncthreads(); }
    if (tid == 0) { g_m[row] = m; g_z[row] = red[0]; }
}

// w[z,k] = sum_q exp(s[q,k]-m_q)/z_q  — grid (64,4) x 256 threads
__global__ void colsum_kernel()
{
    const int zz = blockIdx.x;
    const int col = blockIdx.y * 256 + threadIdx.x;
    __shared__ float sm[S_], sz[S_];
    for (int q = threadIdx.x; q < S_; q += 256) { sm[q] = g_m[zz*S_+q]; sz[q] = 1.0f / g_z[zz*S_+q]; }
    __syncthreads();
    float acc = 0.f;
    const float* sc = g_scores + (size_t)zz * S_ * S_ + col;
    for (int q = 0; q < S_; q++) acc += __expf(sc[(size_t)q * S_] - sm[q]) * sz[q];
    g_w[zz*S_ + col] = acc;
}

__global__ void ctxmean_kernel()
{
    const int z = blockIdx.x;
    const int b = z >> 2, h = z & 3;
    const int d = threadIdx.x;
    __shared__ float w[S_];
    for (int k = d; k < S_; k += 192) w[k] = g_w[z*S_+k];
    __syncthreads();
    float acc = 0.f;
    const float* vb = g_qkv + (size_t)b * S_ * TD_ + 2*D_ + h*HD_ + d;
    for (int k = 0; k < S_; k++) acc += w[k] * vb[(size_t)k * TD_];
    g_ctxmean[b*D_ + h*HD_ + d] = acc * (1.0f / S_);
}

__global__ void idx_kernel(const int* __restrict__ mask)
{
    const int b = blockIdx.x, tid = threadIdx.x;
    __shared__ int red[256];
    int s = 0;
    for (int k = tid; k < S_; k += 256) s += mask[b*S_ + k];
    red[tid] = s; __syncthreads();
    for (int st = 128; st > 0; st >>= 1) { if (tid < st) red[tid] += red[tid+st]; __syncthreads(); }
    if (tid == 0) g_idx[b] = red[0] - 1;
}

__global__ void embed_kernel(
    const float* __restrict__ Wout, const float* __restrict__ bout,
    const float* __restrict__ Wasp, const float* __restrict__ basp,
    const float* __restrict__ Wopi, const float* __restrict__ bopi,
    const float* __restrict__ Wia,  const float* __restrict__ bia,
    const float* __restrict__ Wio,  const float* __restrict__ bio,
    float* __restrict__ out)
{
    const int b = blockIdx.x, tid = threadIdx.x;
    __shared__ float cm[D_], emb[D_], e1s[D_], e2s[D_];
    for (int d = tid; d < D_; d += 256) cm[d] = g_ctxmean[b*D_ + d];
    __syncthreads();
    for (int n = tid; n < D_; n += 256) {
        float a = bout[n];
        const float* wr = Wout + (size_t)n * D_;
        for (int d = 0; d < D_; d++) a += cm[d] * wr[d];
        emb[n] = a;
    }
    __syncthreads();
    for (int n = tid; n < D_; n += 256) {
        float a = basp[n], o = bopi[n];
        const float* wa = Wasp + (size_t)n * D_;
        const float* wo = Wopi + (size_t)n * D_;
        for (int d = 0; d < D_; d++) { a += emb[d] * wa[d]; o += emb[d] * wo[d]; }
        e1s[n] = a; e2s[n] = o;
    }
    __syncthreads();
    for (int d = tid; d < D_; d += 256) {
        g_e1[b*D_ + d] = e1s[d];
        g_e2[b*D_ + d] = e2s[d];
        out[O_E1 + (size_t)b*D_ + d] = e1s[d];
        out[O_E2 + (size_t)b*D_ + d] = e2s[d];
    }
    if (tid < 2) {
        float a = bia[tid];
        const float* w = Wia + (size_t)tid * D_;
        for (int d = 0; d < D_; d++) a += e1s[d] * w[d];
        out[O_IA + b*2 + tid] = a;
    } else if (tid < 4) {
        int c = tid - 2;
        float a = bio[c];
        const float* w = Wio + (size_t)c * D_;
        for (int d = 0; d < D_; d++) a += e2s[d] * w[d];
        out[O_IO + b*2 + c] = a;
    }
}

__global__ void build_se_kernel(const float* __restrict__ x)
{
    const int blk = blockIdx.x;
    const int b = blk >> 10, s = blk & 1023;
    const int idx = g_idx[b];
#pragma unroll
    for (int i = 0; i < 3; i++) {
        int d = threadIdx.x + i * 256;
        float xv = x[(size_t)blk * D_ + d];
        float e1v = g_e1[b*D_ + d], e2v = g_e2[b*D_ + d];
        float v1 = (s == idx) ? e2v : ((s == 0) ? e1v : xv);
        float v2 = (s == 0) ? e1v : ((s == idx) ? e2v : xv);
        g_h1[(size_t)blk * D_ + d] = v1;
        g_h2[(size_t)blk * D_ + d] = v2;
    }
}

// layernorm: fp32 out + fp16 out for next GEMM A
__global__ void ln_kernel(const float* __restrict__ in,
                          const float* __restrict__ g, const float* __restrict__ bt,
                          float* __restrict__ outp, __half* __restrict__ oh)
{
    const int row = blockIdx.x, tid = threadIdx.x;
    const float* r = in + (size_t)row * D_;
    float v0 = r[tid], v1 = r[tid+256], v2 = r[tid+512];
    __shared__ float red[256];
    red[tid] = v0 + v1 + v2; __syncthreads();
    for (int st = 128; st > 0; st >>= 1) { if (tid < st) red[tid] += red[tid+st]; __syncthreads(); }
    float mean = red[0] * (1.0f / D_);
    __syncthreads();
    float d0 = v0 - mean, d1 = v1 - mean, d2 = v2 - mean;
    red[tid] = d0*d0 + d1*d1 + d2*d2; __syncthreads();
    for (int st = 128; st > 0; st >>= 1) { if (tid < st) red[tid] += red[tid+st]; __syncthreads(); }
    float rstd = rsqrtf(red[0] * (1.0f / D_) + 1e-12f);
    float o0 = d0 * rstd * g[tid]     + bt[tid];
    float o1 = d1 * rstd * g[tid+256] + bt[tid+256];
    float o2 = d2 * rstd * g[tid+512] + bt[tid+512];
    float* o = outp + (size_t)row * D_;
    o[tid] = o0; o[tid+256] = o1; o[tid+512] = o2;
    size_t base = (size_t)row * D_;
    oh[base+tid]     = __float2half(o0);
    oh[base+tid+256] = __float2half(o1);
    oh[base+tid+512] = __float2half(o2);
}

__global__ void logits_kernel(const float* __restrict__ in, const float* __restrict__ W,
                              const float* __restrict__ bias, float* __restrict__ outp)
{
    const int row = blockIdx.x, tid = threadIdx.x;
    __shared__ float srow[D_];
    const float* r = in + (size_t)row * D_;
    srow[tid] = r[tid]; srow[tid+256] = r[tid+256]; srow[tid+512] = r[tid+512];
    __syncthreads();
    float a0 = 0.f, a1 = 0.f, a2 = 0.f;
    for (int d = tid; d < D_; d += 256) {
        float x = srow[d];
        a0 += x * W[d]; a1 += x * W[D_ + d]; a2 += x * W[2*D_ + d];
    }
    __shared__ float red[3][256];
    red[0][tid] = a0; red[1][tid] = a1; red[2][tid] = a2;
    __syncthreads();
    for (int st = 128; st > 0; st >>= 1) {
        if (tid < st) {
            red[0][tid] += red[0][tid+st];
            red[1][tid] += red[1][tid+st];
            red[2][tid] += red[2][tid+st];
        }
        __syncthreads();
    }
    if (tid < 3) outp[(size_t)row * C_ + tid] = red[tid][0] + bias[tid];
}

// ============================================================
extern "C" void kernel_launch(void* const* d_in, const int* in_sizes, int n_in,
                              void* d_out, int out_size)
{
    const float* x        = (const float*)d_in[0];
    const int*   mask     = (const int*)  d_in[1];
    const float* mha_in_w = (const float*)d_in[2];
    const float* mha_in_b = (const float*)d_in[3];
    const float* mha_out_w= (const float*)d_in[4];
    const float* mha_out_b= (const float*)d_in[5];
    const float* asp_w    = (const float*)d_in[6];
    const float* asp_b    = (const float*)d_in[7];
    const float* opi_w    = (const float*)d_in[8];
    const float* opi_b    = (const float*)d_in[9];
    const float* ia_w     = (const float*)d_in[10];
    const float* ia_b     = (const float*)d_in[11];
    const float* io_w     = (const float*)d_in[12];
    const float* io_b     = (const float*)d_in[13];
    const float* fwd_iw   = (const float*)d_in[14];
    const float* fwd_ib   = (const float*)d_in[15];
    const float* fwd_ow   = (const float*)d_in[16];
    const float* fwd_ob   = (const float*)d_in[17];
    const float* fwd_g    = (const float*)d_in[18];
    const float* fwd_bt   = (const float*)d_in[19];
    const float* rev_iw   = (const float*)d_in[20];
    const float* rev_ib   = (const float*)d_in[21];
    const float* rev_ow   = (const float*)d_in[22];
    const float* rev_ob   = (const float*)d_in[23];
    const float* rev_g    = (const float*)d_in[24];
    const float* rev_bt   = (const float*)d_in[25];
    const float* cls_a_w  = (const float*)d_in[26];
    const float* cls_a_b  = (const float*)d_in[27];
    const float* cls_o_w  = (const float*)d_in[28];
    const float* cls_o_b  = (const float*)d_in[29];
    float* out = (float*)d_out;

    float *qkvp, *h1, *h2, *tmp, *scoresp;
    __half *ah, *ih, *bh, *qh, *kh;
    cudaGetSymbolAddress((void**)&qkvp,    g_qkv);
    cudaGetSymbolAddress((void**)&scoresp, g_scores);
    cudaGetSymbolAddress((void**)&h1,   g_h1);
    cudaGetSymbolAddress((void**)&h2,   g_h2);
    cudaGetSymbolAddress((void**)&tmp,  g_tmp);
    cudaGetSymbolAddress((void**)&ah,   g_ah);
    cudaGetSymbolAddress((void**)&ih,   g_ih);
    cudaGetSymbolAddress((void**)&bh,   g_bh);
    cudaGetSymbolAddress((void**)&qh,   g_qh);
    cudaGetSymbolAddress((void**)&kh,   g_kh);

    cudaFuncSetAttribute(tc_gemm<0>, cudaFuncAttributeMaxDynamicSharedMemorySize, GSMEM);
    cudaFuncSetAttribute(tc_gemm<1>, cudaFuncAttributeMaxDynamicSharedMemorySize, GSMEM);
    cudaFuncSetAttribute(tc_gemm<2>, cudaFuncAttributeMaxDynamicSharedMemorySize, GSMEM);
    cudaFuncSetAttribute(tc_gemm<3>, cudaFuncAttributeMaxDynamicSharedMemorySize, GSMEM);

    auto cvt = [&](const float* src, __half* dst, size_t n) {
        cvt_kernel<<<(unsigned)((n/4 + 255) / 256), 256>>>(src, dst, n);
    };

    // 1) QKV projection; epilogue packs Q/K fp16 per head
    cvt(x, ah, (size_t)BS_ * D_);
    cvt(mha_in_w, bh, (size_t)TD_ * D_);
    tc_gemm<0><<<dim3(TD_/128, BS_/128, 1), 128, GSMEM>>>(
        ah, 0, bh, 0, qkvp, TD_, 0, nullptr,
        mha_in_b, nullptr, D_, nullptr, qh, kh);

    // 2) attention scores (batched over 64 z) + softmax stats + colsum + ctx mean
    tc_gemm<3><<<dim3(S_/128, S_/128, B_*NH_), 128, GSMEM>>>(
        qh, (long)S_*HD_, kh, (long)S_*HD_, scoresp, S_, (long)S_*S_, nullptr,
        nullptr, nullptr, HD_, mask, nullptr, nullptr);
    rowstats_kernel<<<B_*NH_*S_, 256>>>();
    colsum_kernel<<<dim3(B_*NH_, 4), 256>>>();
    ctxmean_kernel<<<B_*NH_, 192>>>();

    // 3) embedding path
    idx_kernel<<<B_, 256>>>(mask);
    embed_kernel<<<B_, 256>>>(mha_out_w, mha_out_b, asp_w, asp_b, opi_w, opi_b,
                              ia_w, ia_b, io_w, io_b, out);

    // 4) x passthrough
    cudaMemcpyAsync(out + O_X, x, sizeof(float) * (size_t)BS_ * D_, cudaMemcpyDeviceToDevice);

    // 5) build se1/se2
    build_se_kernel<<<BS_, 256>>>(x);

    // 6) decoder stacks on tensor cores
    struct Stack { float* h; const float *iw, *ib, *ow, *ob, *g, *bt; size_t oSE; }
    stacks[2] = {
        { h1, fwd_iw, fwd_ib, fwd_ow, fwd_ob, fwd_g, fwd_bt, O_SE1 },
        { h2, rev_iw, rev_ib, rev_ow, rev_ob, rev_g, rev_bt, O_SE2 },
    };
    for (int s = 0; s < 2; s++) {
        Stack& st = stacks[s];
        cvt(st.h, ah, (size_t)BS_ * D_);
        for (int l = 0; l < NL_; l++) {
            cvt(st.iw + (size_t)l*DFF_*D_, bh, (size_t)DFF_*D_);
            tc_gemm<1><<<dim3(DFF_/128, BS_/128, 1), 128, GSMEM>>>(
                ah, 0, bh, 0, nullptr, DFF_, 0, ih,
                st.ib + (size_t)l*DFF_, nullptr, D_, nullptr, nullptr, nullptr);
            cvt(st.ow + (size_t)l*D_*DFF_, bh, (size_t)D_*DFF_);
            tc_gemm<2><<<dim3(D_/128, BS_/128, 1), 128, GSMEM>>>(
                ih, 0, bh, 0, tmp, D_, 0, nullptr,
                st.ob + (size_t)l*D_, st.h, DFF_, nullptr, nullptr, nullptr);
            float* lnout = (l == NL_-1) ? (out + st.oSE) : st.h;
            ln_kernel<<<BS_, 256>>>(tmp, st.g + (size_t)l*D_, st.bt + (size_t)l*D_, lnout, ah);
        }
    }

    // 7) classifier logits
    logits_kernel<<<BS_, 256>>>(out + O_SE1, cls_a_w, cls_a_b, out + O_LA);
    logits_kernel<<<BS_, 256>>>(out + O_SE2, cls_o_w, cls_o_b, out + O_LO);
}